// round 2
// baseline (speedup 1.0000x reference)
#include <cuda_runtime.h>
#include <math.h>

#define BB 4
#define NN 2048
#define DIMD 1024
#define NE 24
#define NH 8
#define HDD 128
#define NTASKS 9
#define NT (BB*NN)                    /* 8192 tokens */
#define ATT_SCALE 0.08838834764831843f /* 128^-0.5 */

// ---------------- device scratch (static: no allocations allowed) ----------------
static __device__ float g_WgT[(size_t)NTASKS*NE*DIMD];       // gate weights transposed [t][e][d]
static __device__ float g_q  [(size_t)NT*NH*HDD];            // gathered queries [tok*8+h][128]
static __device__ float g_k  [(size_t)NT*HDD];
static __device__ float g_v  [(size_t)NT*HDD];
static __device__ float g_att[(size_t)NT*NH*HDD];            // attention output
static __device__ float g_gates[NT*NH];
static __device__ int   g_topi [NT*NH];
static __device__ int   g_ecount[NE];
static __device__ int   g_eoffset[NE];
static __device__ int   g_efill[NE];
static __device__ int   g_elist[NT*NH];
static __device__ float g_psum[NE];
static __device__ float g_zsum;

// ---------------- helpers ----------------
__device__ __forceinline__ float warp_sum(float v){
#pragma unroll
  for (int off=16; off; off>>=1) v += __shfl_xor_sync(0xffffffffu, v, off);
  return v;
}
__device__ __forceinline__ float warp_max(float v){
#pragma unroll
  for (int off=16; off; off>>=1) v = fmaxf(v, __shfl_xor_sync(0xffffffffu, v, off));
  return v;
}

// ---------------- small setup kernels ----------------
__global__ void zero_small_kernel(){
  int t = threadIdx.x;
  if (t < NE){ g_ecount[t]=0; g_efill[t]=0; g_psum[t]=0.f; }
  if (t==0) g_zsum = 0.f;
}

__global__ void transpose_wg_kernel(const float* __restrict__ Wg){
  int te = blockIdx.x;                // t*NE + e
  int t = te / NE, e = te % NE;
  for (int d = threadIdx.x; d < DIMD; d += blockDim.x)
    g_WgT[(size_t)te*DIMD + d] = Wg[((size_t)t*DIMD + d)*NE + e];
}

// ---------------- gating: logits, softmax stats, top-8, gates ----------------
__global__ __launch_bounds__(256) void gating_kernel(const float* __restrict__ x,
                                                     const int* __restrict__ task_bh){
  int tok = blockIdx.x;
  int b = tok / NN;
  __shared__ float xs[DIMD];
  __shared__ float lg[NE];
  int tid = threadIdx.x;
  // load token row (vectorized)
  {
    int i = tid*4;
    *(float4*)&xs[i] = *(const float4*)&x[(size_t)tok*DIMD + i];
  }
  __syncthreads();
  int task = task_bh[b];
  int wid = tid>>5, lane = tid&31;
#pragma unroll
  for (int i=0;i<3;i++){
    int e = wid*3+i;
    const float* w = g_WgT + ((size_t)task*NE + e)*DIMD;
    float s = 0.f;
#pragma unroll
    for (int d=lane*4; d<DIMD; d+=128){
      float4 a = *(const float4*)&xs[d];
      float4 wv = *(const float4*)&w[d];
      s += a.x*wv.x + a.y*wv.y + a.z*wv.z + a.w*wv.w;
    }
    s = warp_sum(s);
    if (lane==0) lg[e] = s;
  }
  __syncthreads();
  if (wid==0){
    float v = (lane<NE)? lg[lane] : -1e30f;
    float m = warp_max(v);
    float ex = (lane<NE)? __expf(v-m) : 0.f;
    float se = warp_sum(ex);
    float lse = m + logf(se);
    if (lane<NE) atomicAdd(&g_psum[lane], ex/se);
    if (lane==0) atomicAdd(&g_zsum, lse*lse);
  }
  if (tid==0){
    float loc[NE];
#pragma unroll
    for (int e=0;e<NE;e++) loc[e]=lg[e];
    int sel[NH]; float sv[NH];
#pragma unroll
    for (int h=0;h<NH;h++){
      float best = -1e30f; int idx = 0;
      for (int e=0;e<NE;e++){ if (loc[e] > best){ best=loc[e]; idx=e; } }
      sel[h]=idx; sv[h]=best; loc[idx] = -1e30f;
    }
    float mx = sv[0];
    float pe[NH]; float den = 0.f;
#pragma unroll
    for (int h=0;h<NH;h++){ pe[h]=__expf(sv[h]-mx); den += pe[h]; }
    float inv = 1.f/den;
#pragma unroll
    for (int h=0;h<NH;h++){
      g_gates[tok*NH+h] = pe[h]*inv;
      g_topi [tok*NH+h] = sel[h];
      atomicAdd(&g_ecount[sel[h]], 1);
    }
  }
}

__global__ void offsets_kernel(){
  if (threadIdx.x==0){
    int run=0;
    for (int e=0;e<NE;e++){ g_eoffset[e]=run; run += g_ecount[e]; }
  }
}

__global__ void scatter_kernel(){
  int i = blockIdx.x*blockDim.x + threadIdx.x;
  if (i < NT*NH){
    int e = g_topi[i];
    int pos = atomicAdd(&g_efill[e], 1);
    g_elist[g_eoffset[e]+pos] = i;     // i = tok*8 + h
  }
}

// ---------------- kv = x @ Wkv + bkv ----------------
__global__ __launch_bounds__(256) void kv_gemm_kernel(const float* __restrict__ x,
                                                      const float* __restrict__ Wkv,
                                                      const float* __restrict__ bkv){
  __shared__ float As[64*32];
  __shared__ float Bs[32*128];
  int tid = threadIdx.x;
  int tx = tid & 15, ty = tid >> 4;
  int r0 = ty*4;
  int mt = blockIdx.x, nt = blockIdx.y;   // nt: 0 -> k, 1 -> v
  float acc[4][8] = {};
  const float* Arow = x + (size_t)mt*64*DIMD;
  for (int k0=0;k0<DIMD;k0+=32){
#pragma unroll
    for (int j=0;j<2;j++){
      int f = tid + j*256;
      int row = f>>3, kq = f&7;
      *(float4*)&As[row*32+kq*4] = *(const float4*)&Arow[(size_t)row*DIMD + k0 + kq*4];
    }
#pragma unroll
    for (int j=0;j<4;j++){
      int f = tid + j*256;
      int row = f>>5, cq = f&31;
      *(float4*)&Bs[row*128+cq*4] = *(const float4*)&Wkv[(size_t)(k0+row)*(2*HDD) + nt*128 + cq*4];
    }
    __syncthreads();
#pragma unroll
    for (int kk=0;kk<32;kk++){
      float a[4];
#pragma unroll
      for (int i=0;i<4;i++) a[i] = As[(r0+i)*32+kk];
      float4 b0 = *(float4*)&Bs[kk*128 + tx*4];
      float4 b1 = *(float4*)&Bs[kk*128 + 64 + tx*4];
      float bv[8] = {b0.x,b0.y,b0.z,b0.w,b1.x,b1.y,b1.z,b1.w};
#pragma unroll
      for (int i=0;i<4;i++)
#pragma unroll
        for (int c=0;c<8;c++) acc[i][c] += a[i]*bv[c];
    }
    __syncthreads();
  }
  float* dst = nt ? g_v : g_k;
#pragma unroll
  for (int i=0;i<4;i++){
    int row = mt*64 + r0 + i;
#pragma unroll
    for (int u=0;u<2;u++){
      int col = u*64 + tx*4;
      float4 r;
      r.x = acc[i][u*4+0] + bkv[nt*128+col+0];
      r.y = acc[i][u*4+1] + bkv[nt*128+col+1];
      r.z = acc[i][u*4+2] + bkv[nt*128+col+2];
      r.w = acc[i][u*4+3] + bkv[nt*128+col+3];
      *(float4*)&dst[(size_t)row*HDD + col] = r;
    }
  }
}

// ---------------- grouped gather-GEMM: q[slot] = x[tok] @ Wq[e] ----------------
__global__ __launch_bounds__(256) void q_gemm_kernel(const float* __restrict__ x,
                                                     const float* __restrict__ Wq){
  int e = blockIdx.y, mt = blockIdx.x;
  int cnt = g_ecount[e];
  if (mt*64 >= cnt) return;
  __shared__ float As[64*32];
  __shared__ float Bs[32*128];
  __shared__ int rows[64];
  int tid = threadIdx.x;
  if (tid < 64){
    int mi = mt*64 + tid;
    rows[tid] = (mi < cnt) ? g_elist[g_eoffset[e] + mi] : -1;
  }
  __syncthreads();
  int tx=tid&15, ty=tid>>4, r0=ty*4;
  float acc[4][8]={};
  const float* Bb = Wq + (size_t)e*DIMD*HDD;
  for (int k0=0;k0<DIMD;k0+=32){
#pragma unroll
    for (int j=0;j<2;j++){
      int f=tid+j*256; int row=f>>3, kq=f&7;
      int idx = rows[row];
      float4 v = make_float4(0.f,0.f,0.f,0.f);
      if (idx>=0) v = *(const float4*)&x[(size_t)(idx>>3)*DIMD + k0 + kq*4];
      *(float4*)&As[row*32+kq*4] = v;
    }
#pragma unroll
    for (int j=0;j<4;j++){
      int f=tid+j*256; int row=f>>5, cq=f&31;
      *(float4*)&Bs[row*128+cq*4] = *(const float4*)&Bb[(size_t)(k0+row)*HDD + cq*4];
    }
    __syncthreads();
#pragma unroll
    for (int kk=0;kk<32;kk++){
      float a[4];
#pragma unroll
      for (int i=0;i<4;i++) a[i] = As[(r0+i)*32+kk];
      float4 b0 = *(float4*)&Bs[kk*128 + tx*4];
      float4 b1 = *(float4*)&Bs[kk*128 + 64 + tx*4];
      float bv[8] = {b0.x,b0.y,b0.z,b0.w,b1.x,b1.y,b1.z,b1.w};
#pragma unroll
      for (int i=0;i<4;i++)
#pragma unroll
        for (int c=0;c<8;c++) acc[i][c] += a[i]*bv[c];
    }
    __syncthreads();
  }
#pragma unroll
  for (int i=0;i<4;i++){
    int idx = rows[r0+i];
    if (idx<0) continue;
#pragma unroll
    for (int u=0;u<2;u++){
      int col = u*64 + tx*4;
      float4 r = {acc[i][u*4+0],acc[i][u*4+1],acc[i][u*4+2],acc[i][u*4+3]};
      *(float4*)&g_q[(size_t)idx*HDD + col] = r;
    }
  }
}

// ---------------- flash attention (MQA): per (b, h) ----------------
// smem: Qs(64x128) + Kt(128x64) + Vs(64x128); Ps(64x64) aliases the first
// 16KB of Kt (Kt is dead once S is computed; extra barrier guards the alias).
// 96KB total -> 2 CTAs/SM.
#define FLASH_SMEM (24576*4)
__global__ __launch_bounds__(256, 2) void flash_kernel(){
  int mt = blockIdx.x, h = blockIdx.y, b = blockIdx.z;
  extern __shared__ float sm[];
  float* Qs = sm;                 // 64 x 128
  float* Kt = Qs + 64*128;        // 128 x 64 (transposed)
  float* Vs = Kt + 128*64;        // 64 x 128
  float* Ps = Kt;                 // 64 x 64, aliases Kt
  int tid = threadIdx.x;
  int tx = tid & 15, ty = tid >> 4;
  int r0 = ty*4, c0 = tx*4;

  // load Q tile, pre-scaled
#pragma unroll
  for (int j=0;j<8;j++){
    int f = tid + j*256;
    int row = f>>5, dv = f&31;
    size_t qrow = ((size_t)(b*NN + mt*64 + row)*NH + h);
    float4 qv = *(const float4*)&g_q[qrow*HDD + dv*4];
    qv.x*=ATT_SCALE; qv.y*=ATT_SCALE; qv.z*=ATT_SCALE; qv.w*=ATT_SCALE;
    *(float4*)&Qs[row*128 + dv*4] = qv;
  }

  float m_i[4], l_i[4], o[4][8];
#pragma unroll
  for (int i=0;i<4;i++){ m_i[i] = -1e30f; l_i[i] = 0.f;
#pragma unroll
    for (int c=0;c<8;c++) o[i][c]=0.f; }

  for (int nt2=0; nt2<NN/64; nt2++){
    __syncthreads();   // prior P*V fully consumed (Ps aliases Kt); Qs ready on iter 0
#pragma unroll
    for (int j=0;j<8;j++){
      int f = tid + j*256;
      int row = f>>5, dv = f&31;
      size_t grow = (size_t)(b*NN + nt2*64 + row);
      float4 kv4 = *(const float4*)&g_k[grow*HDD + dv*4];
      Kt[(dv*4+0)*64 + row] = kv4.x;
      Kt[(dv*4+1)*64 + row] = kv4.y;
      Kt[(dv*4+2)*64 + row] = kv4.z;
      Kt[(dv*4+3)*64 + row] = kv4.w;
      float4 vv = *(const float4*)&g_v[grow*HDD + dv*4];
      *(float4*)&Vs[row*128 + dv*4] = vv;
    }
    __syncthreads();

    // S = Q K^T tile (4x4 per thread)
    float s[4][4] = {};
#pragma unroll 8
    for (int d=0; d<HDD; d+=4){
      float qv[4][4], kvv[4][4];
#pragma unroll
      for (int i=0;i<4;i++){
        float4 t = *(float4*)&Qs[(r0+i)*128 + d];
        qv[i][0]=t.x; qv[i][1]=t.y; qv[i][2]=t.z; qv[i][3]=t.w;
      }
#pragma unroll
      for (int dd=0;dd<4;dd++){
        float4 t = *(float4*)&Kt[(d+dd)*64 + c0];
        kvv[dd][0]=t.x; kvv[dd][1]=t.y; kvv[dd][2]=t.z; kvv[dd][3]=t.w;
      }
#pragma unroll
      for (int i=0;i<4;i++)
#pragma unroll
        for (int j=0;j<4;j++)
#pragma unroll
          for (int dd=0;dd<4;dd++) s[i][j] += qv[i][dd]*kvv[dd][j];
    }
    __syncthreads();   // all Kt reads done before Ps (alias) is written

    // online softmax update (row reductions over the 16-thread tx group)
#pragma unroll
    for (int i=0;i<4;i++){
      float mx = fmaxf(fmaxf(s[i][0],s[i][1]), fmaxf(s[i][2],s[i][3]));
#pragma unroll
      for (int off=8; off; off>>=1) mx = fmaxf(mx, __shfl_xor_sync(0xffffffffu, mx, off));
      float mn = fmaxf(m_i[i], mx);
      float p0 = __expf(s[i][0]-mn), p1 = __expf(s[i][1]-mn);
      float p2 = __expf(s[i][2]-mn), p3 = __expf(s[i][3]-mn);
      float rs = p0+p1+p2+p3;
#pragma unroll
      for (int off=8; off; off>>=1) rs += __shfl_xor_sync(0xffffffffu, rs, off);
      float alpha = __expf(m_i[i]-mn);
      l_i[i] = l_i[i]*alpha + rs;
      m_i[i] = mn;
#pragma unroll
      for (int c=0;c<8;c++) o[i][c] *= alpha;
      float4 pp = {p0,p1,p2,p3};
      *(float4*)&Ps[(r0+i)*64 + c0] = pp;
    }
    __syncthreads();

    // O += P V
#pragma unroll 4
    for (int j=0;j<64;j++){
      float p[4];
#pragma unroll
      for (int i=0;i<4;i++) p[i] = Ps[(r0+i)*64 + j];
      float4 v0 = *(float4*)&Vs[j*128 + tx*4];
      float4 v1 = *(float4*)&Vs[j*128 + 64 + tx*4];
      float vv[8] = {v0.x,v0.y,v0.z,v0.w,v1.x,v1.y,v1.z,v1.w};
#pragma unroll
      for (int i=0;i<4;i++)
#pragma unroll
        for (int c=0;c<8;c++) o[i][c] += p[i]*vv[c];
    }
  }

  // write normalized output
#pragma unroll
  for (int i=0;i<4;i++){
    float inv = 1.f / l_i[i];
    size_t row = ((size_t)(b*NN + mt*64 + r0 + i)*NH + h);
    float4 w0 = {o[i][0]*inv, o[i][1]*inv, o[i][2]*inv, o[i][3]*inv};
    float4 w1 = {o[i][4]*inv, o[i][5]*inv, o[i][6]*inv, o[i][7]*inv};
    *(float4*)&g_att[row*HDD + tx*4]      = w0;
    *(float4*)&g_att[row*HDD + 64 + tx*4] = w1;
  }
}

// ---------------- grouped output GEMM: y += (gate * att) @ Wo[e] ----------------
__global__ __launch_bounds__(256) void y_gemm_kernel(const float* __restrict__ Wo,
                                                     float* __restrict__ y){
  int e = blockIdx.y, mt = blockIdx.x, nt = blockIdx.z;
  int cnt = g_ecount[e];
  if (mt*64 >= cnt) return;
  __shared__ float As[64*32];
  __shared__ float Bs[32*128];
  __shared__ int rows[64];
  __shared__ float gr[64];
  int tid = threadIdx.x;
  if (tid < 64){
    int mi = mt*64 + tid;
    int idx = (mi < cnt) ? g_elist[g_eoffset[e] + mi] : -1;
    rows[tid] = idx;
    gr[tid] = (idx>=0) ? g_gates[idx] : 0.f;
  }
  __syncthreads();
  int tx=tid&15, ty=tid>>4, r0=ty*4;
  float acc[4][8]={};
  const float* Bb = Wo + (size_t)e*HDD*DIMD + nt*128;
  for (int k0=0;k0<HDD;k0+=32){
#pragma unroll
    for (int j=0;j<2;j++){
      int f=tid+j*256; int row=f>>3, kq=f&7;
      int idx = rows[row];
      float4 v = make_float4(0.f,0.f,0.f,0.f);
      if (idx>=0){
        v = *(const float4*)&g_att[(size_t)idx*HDD + k0 + kq*4];
        float g = gr[row];
        v.x*=g; v.y*=g; v.z*=g; v.w*=g;
      }
      *(float4*)&As[row*32+kq*4] = v;
    }
#pragma unroll
    for (int j=0;j<4;j++){
      int f=tid+j*256; int row=f>>5, cq=f&31;
      *(float4*)&Bs[row*128+cq*4] = *(const float4*)&Bb[(size_t)(k0+row)*DIMD + cq*4];
    }
    __syncthreads();
#pragma unroll
    for (int kk=0;kk<32;kk++){
      float a[4];
#pragma unroll
      for (int i=0;i<4;i++) a[i] = As[(r0+i)*32+kk];
      float4 b0 = *(float4*)&Bs[kk*128 + tx*4];
      float4 b1 = *(float4*)&Bs[kk*128 + 64 + tx*4];
      float bv[8] = {b0.x,b0.y,b0.z,b0.w,b1.x,b1.y,b1.z,b1.w};
#pragma unroll
      for (int i=0;i<4;i++)
#pragma unroll
        for (int c=0;c<8;c++) acc[i][c] += a[i]*bv[c];
    }
    __syncthreads();
  }
#pragma unroll
  for (int i=0;i<4;i++){
    int idx = rows[r0+i];
    if (idx<0) continue;
    int tok = idx >> 3;
#pragma unroll
    for (int u=0;u<2;u++){
      int col = nt*128 + u*64 + tx*4;
#pragma unroll
      for (int q=0;q<4;q++)
        atomicAdd(&y[(size_t)tok*DIMD + col + q], acc[i][u*4+q]);
    }
  }
}

// ---------------- aux loss ----------------
__global__ void aux_kernel(float* __restrict__ out, int out_size){
  int lane = threadIdx.x;
  float v = 0.f;
  if (lane < NE) v = ((float)g_ecount[lane]/(float)NT) * (g_psum[lane]/(float)NT);
  v = warp_sum(v);
  if (lane==0 && out_size > NT*DIMD)
    out[(size_t)NT*DIMD] = 0.1f*NE*v + 0.001f*(g_zsum/(float)NT);
}

// ---------------- launcher ----------------
extern "C" void kernel_launch(void* const* d_in, const int* in_sizes, int n_in,
                              void* d_out, int out_size){
  const float* x       = (const float*)d_in[0];
  const int*   task_bh = (const int*)  d_in[1];
  const float* Wg      = (const float*)d_in[2];
  const float* Wq      = (const float*)d_in[3];
  const float* Wo      = (const float*)d_in[4];
  const float* Wkv     = (const float*)d_in[5];
  const float* bkv     = (const float*)d_in[6];
  float* y = (float*)d_out;

  cudaFuncSetAttribute(flash_kernel, cudaFuncAttributeMaxDynamicSharedMemorySize, FLASH_SMEM);

  cudaMemsetAsync(y, 0, (size_t)NT*DIMD*sizeof(float));
  zero_small_kernel<<<1, 64>>>();
  transpose_wg_kernel<<<NTASKS*NE, 256>>>(Wg);
  gating_kernel<<<NT, 256>>>(x, task_bh);
  offsets_kernel<<<1, 32>>>();
  scatter_kernel<<<(NT*NH)/256, 256>>>();
  kv_gemm_kernel<<<dim3(NT/64, 2), 256>>>(x, Wkv, bkv);
  q_gemm_kernel<<<dim3(NT/64, NE), 256>>>(x, Wq);
  flash_kernel<<<dim3(NN/64, NH, BB), 256, FLASH_SMEM>>>();
  y_gemm_kernel<<<dim3(NT/64, NE, DIMD/128), 256>>>(Wo, y);
  aux_kernel<<<1, 32>>>(y, out_size);
}

// round 3
// speedup vs baseline: 2.0098x; 2.0098x over previous
#include <cuda_runtime.h>
#include <math.h>

#define BB 4
#define NN 2048
#define DIMD 1024
#define NE 24
#define NH 8
#define HDD 128
#define NTASKS 9
#define NT (BB*NN)                    /* 8192 tokens */
#define ATT_SCALE 0.08838834764831843f /* 128^-0.5 */

// ---------------- device scratch (static: no allocations allowed) ----------------
static __device__ float g_WgT[(size_t)NTASKS*NE*DIMD];       // gate weights transposed [t][e][d]
static __device__ float g_q  [(size_t)NT*NH*HDD];            // gathered queries, tf32, pre-scaled
static __device__ float g_k  [(size_t)NT*HDD];               // tf32
static __device__ float g_v  [(size_t)NT*HDD];               // tf32
static __device__ float g_att[(size_t)NT*NH*HDD];            // attention output (fp32)
static __device__ float g_gates[NT*NH];
static __device__ int   g_topi [NT*NH];
static __device__ int   g_ecount[NE];
static __device__ int   g_eoffset[NE];
static __device__ int   g_efill[NE];
static __device__ int   g_elist[NT*NH];
static __device__ float g_psum[NE];
static __device__ float g_zsum;

// ---------------- helpers ----------------
__device__ __forceinline__ float warp_sum(float v){
#pragma unroll
  for (int off=16; off; off>>=1) v += __shfl_xor_sync(0xffffffffu, v, off);
  return v;
}
__device__ __forceinline__ float warp_max(float v){
#pragma unroll
  for (int off=16; off; off>>=1) v = fmaxf(v, __shfl_xor_sync(0xffffffffu, v, off));
  return v;
}
__device__ __forceinline__ float to_tf32(float x){
  unsigned u;
  asm("cvt.rna.tf32.f32 %0, %1;" : "=r"(u) : "f"(x));
  return __uint_as_float(u);
}
__device__ __forceinline__ void mma_tf32(float c[4],
    unsigned a0, unsigned a1, unsigned a2, unsigned a3,
    unsigned b0, unsigned b1){
  asm volatile("mma.sync.aligned.m16n8k8.row.col.f32.tf32.tf32.f32 "
    "{%0,%1,%2,%3}, {%4,%5,%6,%7}, {%8,%9}, {%0,%1,%2,%3};"
    : "+f"(c[0]), "+f"(c[1]), "+f"(c[2]), "+f"(c[3])
    : "r"(a0), "r"(a1), "r"(a2), "r"(a3), "r"(b0), "r"(b1));
}

// ---------------- small setup kernels ----------------
__global__ void zero_small_kernel(){
  int t = threadIdx.x;
  if (t < NE){ g_ecount[t]=0; g_efill[t]=0; g_psum[t]=0.f; }
  if (t==0) g_zsum = 0.f;
}

__global__ void transpose_wg_kernel(const float* __restrict__ Wg){
  int te = blockIdx.x;                // t*NE + e
  int t = te / NE, e = te % NE;
  for (int d = threadIdx.x; d < DIMD; d += blockDim.x)
    g_WgT[(size_t)te*DIMD + d] = Wg[((size_t)t*DIMD + d)*NE + e];
}

// ---------------- gating: logits, softmax stats, top-8, gates ----------------
__global__ __launch_bounds__(256) void gating_kernel(const float* __restrict__ x,
                                                     const int* __restrict__ task_bh){
  int tok = blockIdx.x;
  int b = tok / NN;
  __shared__ float xs[DIMD];
  __shared__ float lg[NE];
  int tid = threadIdx.x;
  {
    int i = tid*4;
    *(float4*)&xs[i] = *(const float4*)&x[(size_t)tok*DIMD + i];
  }
  __syncthreads();
  int task = task_bh[b];
  int wid = tid>>5, lane = tid&31;
#pragma unroll
  for (int i=0;i<3;i++){
    int e = wid*3+i;
    const float* w = g_WgT + ((size_t)task*NE + e)*DIMD;
    float s = 0.f;
#pragma unroll
    for (int d=lane*4; d<DIMD; d+=128){
      float4 a = *(const float4*)&xs[d];
      float4 wv = *(const float4*)&w[d];
      s += a.x*wv.x + a.y*wv.y + a.z*wv.z + a.w*wv.w;
    }
    s = warp_sum(s);
    if (lane==0) lg[e] = s;
  }
  __syncthreads();
  if (wid==0){
    float v = (lane<NE)? lg[lane] : -1e30f;
    float m = warp_max(v);
    float ex = (lane<NE)? __expf(v-m) : 0.f;
    float se = warp_sum(ex);
    float lse = m + logf(se);
    if (lane<NE) atomicAdd(&g_psum[lane], ex/se);
    if (lane==0) atomicAdd(&g_zsum, lse*lse);
  }
  if (tid==0){
    float loc[NE];
#pragma unroll
    for (int e=0;e<NE;e++) loc[e]=lg[e];
    int sel[NH]; float sv[NH];
#pragma unroll
    for (int h=0;h<NH;h++){
      float best = -1e30f; int idx = 0;
      for (int e=0;e<NE;e++){ if (loc[e] > best){ best=loc[e]; idx=e; } }
      sel[h]=idx; sv[h]=best; loc[idx] = -1e30f;
    }
    float mx = sv[0];
    float pe[NH]; float den = 0.f;
#pragma unroll
    for (int h=0;h<NH;h++){ pe[h]=__expf(sv[h]-mx); den += pe[h]; }
    float inv = 1.f/den;
#pragma unroll
    for (int h=0;h<NH;h++){
      g_gates[tok*NH+h] = pe[h]*inv;
      g_topi [tok*NH+h] = sel[h];
      atomicAdd(&g_ecount[sel[h]], 1);
    }
  }
}

__global__ void offsets_kernel(){
  if (threadIdx.x==0){
    int run=0;
    for (int e=0;e<NE;e++){ g_eoffset[e]=run; run += g_ecount[e]; }
  }
}

__global__ void scatter_kernel(){
  int i = blockIdx.x*blockDim.x + threadIdx.x;
  if (i < NT*NH){
    int e = g_topi[i];
    int pos = atomicAdd(&g_efill[e], 1);
    g_elist[g_eoffset[e]+pos] = i;     // i = tok*8 + h
  }
}

// ---------------- kv = x @ Wkv + bkv  (tf32-rounded output for flash) ----------------
__global__ __launch_bounds__(256) void kv_gemm_kernel(const float* __restrict__ x,
                                                      const float* __restrict__ Wkv,
                                                      const float* __restrict__ bkv){
  __shared__ float As[64*32];
  __shared__ float Bs[32*128];
  int tid = threadIdx.x;
  int tx = tid & 15, ty = tid >> 4;
  int r0 = ty*4;
  int mt = blockIdx.x, nt = blockIdx.y;   // nt: 0 -> k, 1 -> v
  float acc[4][8] = {};
  const float* Arow = x + (size_t)mt*64*DIMD;
  for (int k0=0;k0<DIMD;k0+=32){
#pragma unroll
    for (int j=0;j<2;j++){
      int f = tid + j*256;
      int row = f>>3, kq = f&7;
      *(float4*)&As[row*32+kq*4] = *(const float4*)&Arow[(size_t)row*DIMD + k0 + kq*4];
    }
#pragma unroll
    for (int j=0;j<4;j++){
      int f = tid + j*256;
      int row = f>>5, cq = f&31;
      *(float4*)&Bs[row*128+cq*4] = *(const float4*)&Wkv[(size_t)(k0+row)*(2*HDD) + nt*128 + cq*4];
    }
    __syncthreads();
#pragma unroll
    for (int kk=0;kk<32;kk++){
      float a[4];
#pragma unroll
      for (int i=0;i<4;i++) a[i] = As[(r0+i)*32+kk];
      float4 b0 = *(float4*)&Bs[kk*128 + tx*4];
      float4 b1 = *(float4*)&Bs[kk*128 + 64 + tx*4];
      float bv[8] = {b0.x,b0.y,b0.z,b0.w,b1.x,b1.y,b1.z,b1.w};
#pragma unroll
      for (int i=0;i<4;i++)
#pragma unroll
        for (int c=0;c<8;c++) acc[i][c] += a[i]*bv[c];
    }
    __syncthreads();
  }
  float* dst = nt ? g_v : g_k;
#pragma unroll
  for (int i=0;i<4;i++){
    int row = mt*64 + r0 + i;
#pragma unroll
    for (int u=0;u<2;u++){
      int col = u*64 + tx*4;
      float4 r;
      r.x = to_tf32(acc[i][u*4+0] + bkv[nt*128+col+0]);
      r.y = to_tf32(acc[i][u*4+1] + bkv[nt*128+col+1]);
      r.z = to_tf32(acc[i][u*4+2] + bkv[nt*128+col+2]);
      r.w = to_tf32(acc[i][u*4+3] + bkv[nt*128+col+3]);
      *(float4*)&dst[(size_t)row*HDD + col] = r;
    }
  }
}

// ---------------- grouped gather-GEMM: q[slot] = x[tok] @ Wq[e] (tf32+scale out) ----------------
__global__ __launch_bounds__(256) void q_gemm_kernel(const float* __restrict__ x,
                                                     const float* __restrict__ Wq){
  int e = blockIdx.y, mt = blockIdx.x;
  int cnt = g_ecount[e];
  if (mt*64 >= cnt) return;
  __shared__ float As[64*32];
  __shared__ float Bs[32*128];
  __shared__ int rows[64];
  int tid = threadIdx.x;
  if (tid < 64){
    int mi = mt*64 + tid;
    rows[tid] = (mi < cnt) ? g_elist[g_eoffset[e] + mi] : -1;
  }
  __syncthreads();
  int tx=tid&15, ty=tid>>4, r0=ty*4;
  float acc[4][8]={};
  const float* Bb = Wq + (size_t)e*DIMD*HDD;
  for (int k0=0;k0<DIMD;k0+=32){
#pragma unroll
    for (int j=0;j<2;j++){
      int f=tid+j*256; int row=f>>3, kq=f&7;
      int idx = rows[row];
      float4 v = make_float4(0.f,0.f,0.f,0.f);
      if (idx>=0) v = *(const float4*)&x[(size_t)(idx>>3)*DIMD + k0 + kq*4];
      *(float4*)&As[row*32+kq*4] = v;
    }
#pragma unroll
    for (int j=0;j<4;j++){
      int f=tid+j*256; int row=f>>5, cq=f&31;
      *(float4*)&Bs[row*128+cq*4] = *(const float4*)&Bb[(size_t)(k0+row)*HDD + cq*4];
    }
    __syncthreads();
#pragma unroll
    for (int kk=0;kk<32;kk++){
      float a[4];
#pragma unroll
      for (int i=0;i<4;i++) a[i] = As[(r0+i)*32+kk];
      float4 b0 = *(float4*)&Bs[kk*128 + tx*4];
      float4 b1 = *(float4*)&Bs[kk*128 + 64 + tx*4];
      float bv[8] = {b0.x,b0.y,b0.z,b0.w,b1.x,b1.y,b1.z,b1.w};
#pragma unroll
      for (int i=0;i<4;i++)
#pragma unroll
        for (int c=0;c<8;c++) acc[i][c] += a[i]*bv[c];
    }
    __syncthreads();
  }
#pragma unroll
  for (int i=0;i<4;i++){
    int idx = rows[r0+i];
    if (idx<0) continue;
#pragma unroll
    for (int u=0;u<2;u++){
      int col = u*64 + tx*4;
      float4 r = {to_tf32(acc[i][u*4+0]*ATT_SCALE), to_tf32(acc[i][u*4+1]*ATT_SCALE),
                  to_tf32(acc[i][u*4+2]*ATT_SCALE), to_tf32(acc[i][u*4+3]*ATT_SCALE)};
      *(float4*)&g_q[(size_t)idx*HDD + col] = r;
    }
  }
}

// ---------------- flash attention (MQA) with tf32 mma.sync ----------------
// smem: Qs 64x132, Ks 64x132, Vs 64x136, Ps 64x68, pmax/psum 2x64 each.
// strides: 132 (=4 mod 32) conflict-free for gid-row frags; 136 (=8 mod 32) for tid4-row (V).
#define Q_STR 132
#define K_STR 132
#define V_STR 136
#define P_STR 68
#define FLASH_SMEM ((64*Q_STR + 64*K_STR + 64*V_STR + 64*P_STR + 256)*4)
__global__ __launch_bounds__(256, 1) void flash_kernel(){
  int mt = blockIdx.x, h = blockIdx.y, b = blockIdx.z;
  extern __shared__ float sm[];
  float* Qs   = sm;
  float* Ks   = Qs + 64*Q_STR;
  float* Vs   = Ks + 64*K_STR;
  float* Ps   = Vs + 64*V_STR;
  float* pmax = Ps + 64*P_STR;   // [2][64]
  float* psum = pmax + 128;      // [2][64]
  int tid  = threadIdx.x;
  int wid  = tid >> 5, lane = tid & 31;
  int wm = wid & 3, wn = wid >> 2;
  int gid = lane >> 2, tid4 = lane & 3;
  int m0 = wm*16;

  // load Q tile (already tf32 + pre-scaled)
#pragma unroll
  for (int j=0;j<8;j++){
    int f = tid + j*256;
    int row = f>>5, dv = f&31;
    float4 qv = *(const float4*)&g_q[((size_t)(b*NN + mt*64 + row)*NH + h)*HDD + dv*4];
    *(float4*)&Qs[row*Q_STR + dv*4] = qv;
  }

  float m_i[2] = {-1e30f, -1e30f}, l_i[2] = {0.f, 0.f};
  float oc[8][4];
#pragma unroll
  for (int j=0;j<8;j++){ oc[j][0]=0.f; oc[j][1]=0.f; oc[j][2]=0.f; oc[j][3]=0.f; }

  for (int nt2=0; nt2<NN/64; nt2++){
    __syncthreads();   // previous tile's smem fully consumed (Qs ready on iter 0)
#pragma unroll
    for (int j=0;j<8;j++){
      int f = tid + j*256;
      int row = f>>5, dv = f&31;
      size_t grow = (size_t)(b*NN + nt2*64 + row);
      *(float4*)&Ks[row*K_STR + dv*4] = *(const float4*)&g_k[grow*HDD + dv*4];
      *(float4*)&Vs[row*V_STR + dv*4] = *(const float4*)&g_v[grow*HDD + dv*4];
    }
    __syncthreads();

    // ---- S = Q K^T : warp computes rows m0..m0+15, cols 32*wn..+31
    float sc[4][4];
#pragma unroll
    for (int j=0;j<4;j++){ sc[j][0]=0.f; sc[j][1]=0.f; sc[j][2]=0.f; sc[j][3]=0.f; }
#pragma unroll
    for (int kt=0; kt<16; kt++){
      int k0 = kt*8;
      unsigned a0 = __float_as_uint(Qs[(m0+gid)  *Q_STR + k0 + tid4]);
      unsigned a1 = __float_as_uint(Qs[(m0+8+gid)*Q_STR + k0 + tid4]);
      unsigned a2 = __float_as_uint(Qs[(m0+gid)  *Q_STR + k0 + tid4 + 4]);
      unsigned a3 = __float_as_uint(Qs[(m0+8+gid)*Q_STR + k0 + tid4 + 4]);
#pragma unroll
      for (int j=0;j<4;j++){
        int n0 = wn*32 + j*8;
        unsigned b0 = __float_as_uint(Ks[(n0+gid)*K_STR + k0 + tid4]);
        unsigned b1 = __float_as_uint(Ks[(n0+gid)*K_STR + k0 + tid4 + 4]);
        mma_tf32(sc[j], a0,a1,a2,a3, b0,b1);
      }
    }

    // ---- per-warp row max (32 cols), combine across wn via smem
    float mx0 = fmaxf(fmaxf(sc[0][0],sc[0][1]), fmaxf(sc[1][0],sc[1][1]));
    mx0 = fmaxf(mx0, fmaxf(fmaxf(sc[2][0],sc[2][1]), fmaxf(sc[3][0],sc[3][1])));
    float mx1 = fmaxf(fmaxf(sc[0][2],sc[0][3]), fmaxf(sc[1][2],sc[1][3]));
    mx1 = fmaxf(mx1, fmaxf(fmaxf(sc[2][2],sc[2][3]), fmaxf(sc[3][2],sc[3][3])));
    mx0 = fmaxf(mx0, __shfl_xor_sync(0xffffffffu, mx0, 1));
    mx0 = fmaxf(mx0, __shfl_xor_sync(0xffffffffu, mx0, 2));
    mx1 = fmaxf(mx1, __shfl_xor_sync(0xffffffffu, mx1, 1));
    mx1 = fmaxf(mx1, __shfl_xor_sync(0xffffffffu, mx1, 2));
    if (tid4==0){
      pmax[wn*64 + m0 + gid]     = mx0;
      pmax[wn*64 + m0 + 8 + gid] = mx1;
    }
    __syncthreads();
    float mn0 = fmaxf(m_i[0], fmaxf(pmax[m0+gid],   pmax[64+m0+gid]));
    float mn1 = fmaxf(m_i[1], fmaxf(pmax[m0+8+gid], pmax[64+m0+8+gid]));

    // ---- P = exp(S - m), store tf32 to smem, partial row sums
    float rs0 = 0.f, rs1 = 0.f;
#pragma unroll
    for (int j=0;j<4;j++){
      int cc = wn*32 + j*8 + 2*tid4;
      float p00 = __expf(sc[j][0]-mn0), p01 = __expf(sc[j][1]-mn0);
      float p10 = __expf(sc[j][2]-mn1), p11 = __expf(sc[j][3]-mn1);
      rs0 += p00 + p01; rs1 += p10 + p11;
      Ps[(m0+gid)*P_STR   + cc]   = to_tf32(p00);
      Ps[(m0+gid)*P_STR   + cc+1] = to_tf32(p01);
      Ps[(m0+8+gid)*P_STR + cc]   = to_tf32(p10);
      Ps[(m0+8+gid)*P_STR + cc+1] = to_tf32(p11);
    }
    rs0 += __shfl_xor_sync(0xffffffffu, rs0, 1);
    rs0 += __shfl_xor_sync(0xffffffffu, rs0, 2);
    rs1 += __shfl_xor_sync(0xffffffffu, rs1, 1);
    rs1 += __shfl_xor_sync(0xffffffffu, rs1, 2);
    if (tid4==0){
      psum[wn*64 + m0 + gid]     = rs0;
      psum[wn*64 + m0 + 8 + gid] = rs1;
    }
    __syncthreads();
    float gs0 = psum[m0+gid]   + psum[64+m0+gid];
    float gs1 = psum[m0+8+gid] + psum[64+m0+8+gid];
    float al0 = __expf(m_i[0]-mn0), al1 = __expf(m_i[1]-mn1);
    l_i[0] = l_i[0]*al0 + gs0; l_i[1] = l_i[1]*al1 + gs1;
    m_i[0] = mn0; m_i[1] = mn1;
#pragma unroll
    for (int j=0;j<8;j++){ oc[j][0]*=al0; oc[j][1]*=al0; oc[j][2]*=al1; oc[j][3]*=al1; }

    // ---- O += P V : warp computes rows m0..m0+15, cols 64*wn..+63
#pragma unroll
    for (int kt=0; kt<8; kt++){
      int k0 = kt*8;
      unsigned a0 = __float_as_uint(Ps[(m0+gid)  *P_STR + k0 + tid4]);
      unsigned a1 = __float_as_uint(Ps[(m0+8+gid)*P_STR + k0 + tid4]);
      unsigned a2 = __float_as_uint(Ps[(m0+gid)  *P_STR + k0 + tid4 + 4]);
      unsigned a3 = __float_as_uint(Ps[(m0+8+gid)*P_STR + k0 + tid4 + 4]);
#pragma unroll
      for (int j=0;j<8;j++){
        int n0 = wn*64 + j*8;
        unsigned b0 = __float_as_uint(Vs[(k0+tid4)  *V_STR + n0 + gid]);
        unsigned b1 = __float_as_uint(Vs[(k0+tid4+4)*V_STR + n0 + gid]);
        mma_tf32(oc[j], a0,a1,a2,a3, b0,b1);
      }
    }
  }

  // epilogue: normalize, write fp32
  float inv0 = 1.f/l_i[0], inv1 = 1.f/l_i[1];
  size_t base0 = ((size_t)(b*NN + mt*64 + m0 + gid)*NH + h)*HDD;
  size_t base1 = ((size_t)(b*NN + mt*64 + m0 + 8 + gid)*NH + h)*HDD;
#pragma unroll
  for (int j=0;j<8;j++){
    int col = wn*64 + j*8 + 2*tid4;
    *(float2*)&g_att[base0 + col] = make_float2(oc[j][0]*inv0, oc[j][1]*inv0);
    *(float2*)&g_att[base1 + col] = make_float2(oc[j][2]*inv1, oc[j][3]*inv1);
  }
}

// ---------------- grouped output GEMM: y += (gate * att) @ Wo[e] ----------------
__global__ __launch_bounds__(256) void y_gemm_kernel(const float* __restrict__ Wo,
                                                     float* __restrict__ y){
  int e = blockIdx.y, mt = blockIdx.x, nt = blockIdx.z;
  int cnt = g_ecount[e];
  if (mt*64 >= cnt) return;
  __shared__ float As[64*32];
  __shared__ float Bs[32*128];
  __shared__ int rows[64];
  __shared__ float gr[64];
  int tid = threadIdx.x;
  if (tid < 64){
    int mi = mt*64 + tid;
    int idx = (mi < cnt) ? g_elist[g_eoffset[e] + mi] : -1;
    rows[tid] = idx;
    gr[tid] = (idx>=0) ? g_gates[idx] : 0.f;
  }
  __syncthreads();
  int tx=tid&15, ty=tid>>4, r0=ty*4;
  float acc[4][8]={};
  const float* Bb = Wo + (size_t)e*HDD*DIMD + nt*128;
  for (int k0=0;k0<HDD;k0+=32){
#pragma unroll
    for (int j=0;j<2;j++){
      int f=tid+j*256; int row=f>>3, kq=f&7;
      int idx = rows[row];
      float4 v = make_float4(0.f,0.f,0.f,0.f);
      if (idx>=0){
        v = *(const float4*)&g_att[(size_t)idx*HDD + k0 + kq*4];
        float g = gr[row];
        v.x*=g; v.y*=g; v.z*=g; v.w*=g;
      }
      *(float4*)&As[row*32+kq*4] = v;
    }
#pragma unroll
    for (int j=0;j<4;j++){
      int f=tid+j*256; int row=f>>5, cq=f&31;
      *(float4*)&Bs[row*128+cq*4] = *(const float4*)&Bb[(size_t)(k0+row)*DIMD + cq*4];
    }
    __syncthreads();
#pragma unroll
    for (int kk=0;kk<32;kk++){
      float a[4];
#pragma unroll
      for (int i=0;i<4;i++) a[i] = As[(r0+i)*32+kk];
      float4 b0 = *(float4*)&Bs[kk*128 + tx*4];
      float4 b1 = *(float4*)&Bs[kk*128 + 64 + tx*4];
      float bv[8] = {b0.x,b0.y,b0.z,b0.w,b1.x,b1.y,b1.z,b1.w};
#pragma unroll
      for (int i=0;i<4;i++)
#pragma unroll
        for (int c=0;c<8;c++) acc[i][c] += a[i]*bv[c];
    }
    __syncthreads();
  }
#pragma unroll
  for (int i=0;i<4;i++){
    int idx = rows[r0+i];
    if (idx<0) continue;
    int tok = idx >> 3;
#pragma unroll
    for (int u=0;u<2;u++){
      int col = nt*128 + u*64 + tx*4;
#pragma unroll
      for (int q=0;q<4;q++)
        atomicAdd(&y[(size_t)tok*DIMD + col + q], acc[i][u*4+q]);
    }
  }
}

// ---------------- aux loss ----------------
__global__ void aux_kernel(float* __restrict__ out, int out_size){
  int lane = threadIdx.x;
  float v = 0.f;
  if (lane < NE) v = ((float)g_ecount[lane]/(float)NT) * (g_psum[lane]/(float)NT);
  v = warp_sum(v);
  if (lane==0 && out_size > NT*DIMD)
    out[(size_t)NT*DIMD] = 0.1f*NE*v + 0.001f*(g_zsum/(float)NT);
}

// ---------------- launcher ----------------
extern "C" void kernel_launch(void* const* d_in, const int* in_sizes, int n_in,
                              void* d_out, int out_size){
  const float* x       = (const float*)d_in[0];
  const int*   task_bh = (const int*)  d_in[1];
  const float* Wg      = (const float*)d_in[2];
  const float* Wq      = (const float*)d_in[3];
  const float* Wo      = (const float*)d_in[4];
  const float* Wkv     = (const float*)d_in[5];
  const float* bkv     = (const float*)d_in[6];
  float* y = (float*)d_out;

  cudaFuncSetAttribute(flash_kernel, cudaFuncAttributeMaxDynamicSharedMemorySize, FLASH_SMEM);

  cudaMemsetAsync(y, 0, (size_t)NT*DIMD*sizeof(float));
  zero_small_kernel<<<1, 64>>>();
  transpose_wg_kernel<<<NTASKS*NE, 256>>>(Wg);
  gating_kernel<<<NT, 256>>>(x, task_bh);
  offsets_kernel<<<1, 32>>>();
  scatter_kernel<<<(NT*NH)/256, 256>>>();
  kv_gemm_kernel<<<dim3(NT/64, 2), 256>>>(x, Wkv, bkv);
  q_gemm_kernel<<<dim3(NT/64, NE), 256>>>(x, Wq);
  flash_kernel<<<dim3(NN/64, NH, BB), 256, FLASH_SMEM>>>();
  y_gemm_kernel<<<dim3(NT/64, NE, DIMD/128), 256>>>(Wo, y);
  aux_kernel<<<1, 32>>>(y, out_size);
}

// round 9
// speedup vs baseline: 2.9575x; 1.4715x over previous
#include <cuda_runtime.h>
#include <math.h>

#define BB 4
#define NN 2048
#define DIMD 1024
#define NE 24
#define NH 8
#define HDD 128
#define NTASKS 9
#define NT (BB*NN)                    /* 8192 tokens */
#define ATT_SCALE 0.08838834764831843f /* 128^-0.5 */

// ---------------- device scratch (static: no allocations allowed) ----------------
static __device__ float g_WgT[(size_t)NTASKS*NE*DIMD];       // gate weights transposed [t][e][d]
static __device__ float g_q  [(size_t)NT*NH*HDD];            // gathered queries, tf32, pre-scaled
static __device__ float g_k  [(size_t)NT*HDD];               // tf32
static __device__ float g_v  [(size_t)NT*HDD];               // tf32
static __device__ float g_att[(size_t)NT*NH*HDD];            // attention output (fp32)
static __device__ float g_gates[NT*NH];
static __device__ int   g_topi [NT*NH];
static __device__ int   g_ecount[NE];
static __device__ int   g_eoffset[NE];
static __device__ int   g_efill[NE];
static __device__ int   g_elist[NT*NH];                      // slot -> (tok*8+h)
static __device__ float g_psum[NE];
static __device__ float g_zsum;

// ---------------- helpers ----------------
__device__ __forceinline__ float warp_sum(float v){
#pragma unroll
  for (int off=16; off; off>>=1) v += __shfl_xor_sync(0xffffffffu, v, off);
  return v;
}
__device__ __forceinline__ float warp_max(float v){
#pragma unroll
  for (int off=16; off; off>>=1) v = fmaxf(v, __shfl_xor_sync(0xffffffffu, v, off));
  return v;
}
__device__ __forceinline__ float to_tf32(float x){
  unsigned u;
  asm("cvt.rna.tf32.f32 %0, %1;" : "=r"(u) : "f"(x));
  return __uint_as_float(u);
}
__device__ __forceinline__ void mma_tf32(float c[4],
    unsigned a0, unsigned a1, unsigned a2, unsigned a3,
    unsigned b0, unsigned b1){
  asm volatile("mma.sync.aligned.m16n8k8.row.col.f32.tf32.tf32.f32 "
    "{%0,%1,%2,%3}, {%4,%5,%6,%7}, {%8,%9}, {%0,%1,%2,%3};"
    : "+f"(c[0]), "+f"(c[1]), "+f"(c[2]), "+f"(c[3])
    : "r"(a0), "r"(a1), "r"(a2), "r"(a3), "r"(b0), "r"(b1));
}

#define A_STR 36    /* = 4 mod 32: conflict-free for gid-row A frags */
#define B_STR 136   /* = 8 mod 32: conflict-free for tid4-row B frags */

// ---------------- small setup kernels ----------------
__global__ void zero_small_kernel(){
  int t = threadIdx.x;
  if (t < NE){ g_ecount[t]=0; g_efill[t]=0; g_psum[t]=0.f; }
  if (t==0) g_zsum = 0.f;
}

__global__ void transpose_wg_kernel(const float* __restrict__ Wg){
  int te = blockIdx.x;                // t*NE + e
  int t = te / NE, e = te % NE;
  for (int d = threadIdx.x; d < DIMD; d += blockDim.x)
    g_WgT[(size_t)te*DIMD + d] = Wg[((size_t)t*DIMD + d)*NE + e];
}

// ---------------- gating: logits, softmax stats, top-8, gates ----------------
__global__ __launch_bounds__(256) void gating_kernel(const float* __restrict__ x,
                                                     const int* __restrict__ task_bh){
  int tok = blockIdx.x;
  int b = tok / NN;
  __shared__ float xs[DIMD];
  __shared__ float lg[NE];
  int tid = threadIdx.x;
  {
    int i = tid*4;
    *(float4*)&xs[i] = *(const float4*)&x[(size_t)tok*DIMD + i];
  }
  __syncthreads();
  int task = task_bh[b];
  int wid = tid>>5, lane = tid&31;
#pragma unroll
  for (int i=0;i<3;i++){
    int e = wid*3+i;
    const float* w = g_WgT + ((size_t)task*NE + e)*DIMD;
    float s = 0.f;
#pragma unroll
    for (int d=lane*4; d<DIMD; d+=128){
      float4 a = *(const float4*)&xs[d];
      float4 wv = *(const float4*)&w[d];
      s += a.x*wv.x + a.y*wv.y + a.z*wv.z + a.w*wv.w;
    }
    s = warp_sum(s);
    if (lane==0) lg[e] = s;
  }
  __syncthreads();
  if (wid==0){
    float v = (lane<NE)? lg[lane] : -1e30f;
    float m = warp_max(v);
    float ex = (lane<NE)? __expf(v-m) : 0.f;
    float se = warp_sum(ex);
    float lse = m + logf(se);
    if (lane<NE) atomicAdd(&g_psum[lane], ex/se);
    if (lane==0) atomicAdd(&g_zsum, lse*lse);
  }
  if (tid==0){
    float loc[NE];
#pragma unroll
    for (int e=0;e<NE;e++) loc[e]=lg[e];
    int sel[NH]; float sv[NH];
#pragma unroll
    for (int h=0;h<NH;h++){
      float best = -1e30f; int idx = 0;
      for (int e=0;e<NE;e++){ if (loc[e] > best){ best=loc[e]; idx=e; } }
      sel[h]=idx; sv[h]=best; loc[idx] = -1e30f;
    }
    float mx = sv[0];
    float pe[NH]; float den = 0.f;
#pragma unroll
    for (int h=0;h<NH;h++){ pe[h]=__expf(sv[h]-mx); den += pe[h]; }
    float inv = 1.f/den;
#pragma unroll
    for (int h=0;h<NH;h++){
      g_gates[tok*NH+h] = pe[h]*inv;
      g_topi [tok*NH+h] = sel[h];
      atomicAdd(&g_ecount[sel[h]], 1);
    }
  }
}

__global__ void offsets_kernel(){
  if (threadIdx.x==0){
    int run=0;
    for (int e=0;e<NE;e++){ g_eoffset[e]=run; run += g_ecount[e]; }
  }
}

__global__ void scatter_kernel(){
  int i = blockIdx.x*blockDim.x + threadIdx.x;
  if (i < NT*NH){
    int e = g_topi[i];
    int pos = atomicAdd(&g_efill[e], 1);
    g_elist[g_eoffset[e]+pos] = i;     // i = tok*8 + h
  }
}

// ---------------- kv = x @ Wkv + bkv  (tf32 mma, tf32-rounded output) ----------------
__global__ __launch_bounds__(256) void kv_mma_kernel(const float* __restrict__ x,
                                                     const float* __restrict__ Wkv,
                                                     const float* __restrict__ bkv){
  __shared__ float As[64*A_STR];
  __shared__ float Bs[32*B_STR];
  int mt = blockIdx.x, nt = blockIdx.y;   // nt: 0 -> k, 1 -> v
  int tid = threadIdx.x;
  int wid = tid>>5, lane = tid&31;
  int wm = wid&3, wn = wid>>2;
  int gid = lane>>2, tid4 = lane&3;
  int m0 = wm*16;
  float oc[8][4];
#pragma unroll
  for (int j=0;j<8;j++){ oc[j][0]=0.f; oc[j][1]=0.f; oc[j][2]=0.f; oc[j][3]=0.f; }
  const float* Arow = x + (size_t)mt*64*DIMD;

  for (int k0g=0;k0g<DIMD;k0g+=32){
    __syncthreads();
#pragma unroll
    for (int j=0;j<2;j++){
      int f = tid + j*256; int row = f>>3, kq = f&7;
      float4 v = *(const float4*)&Arow[(size_t)row*DIMD + k0g + kq*4];
      float4 r = {to_tf32(v.x), to_tf32(v.y), to_tf32(v.z), to_tf32(v.w)};
      *(float4*)&As[row*A_STR + kq*4] = r;
    }
#pragma unroll
    for (int j=0;j<4;j++){
      int f = tid + j*256; int row = f>>5, nq = f&31;
      float4 v = *(const float4*)&Wkv[(size_t)(k0g+row)*(2*HDD) + nt*128 + nq*4];
      float4 r = {to_tf32(v.x), to_tf32(v.y), to_tf32(v.z), to_tf32(v.w)};
      *(float4*)&Bs[row*B_STR + nq*4] = r;
    }
    __syncthreads();
#pragma unroll
    for (int kt=0;kt<4;kt++){
      int k0 = kt*8;
      unsigned a0 = __float_as_uint(As[(m0+gid)  *A_STR + k0 + tid4]);
      unsigned a1 = __float_as_uint(As[(m0+8+gid)*A_STR + k0 + tid4]);
      unsigned a2 = __float_as_uint(As[(m0+gid)  *A_STR + k0 + tid4 + 4]);
      unsigned a3 = __float_as_uint(As[(m0+8+gid)*A_STR + k0 + tid4 + 4]);
#pragma unroll
      for (int j=0;j<8;j++){
        int n0 = wn*64 + j*8;
        unsigned b0 = __float_as_uint(Bs[(k0+tid4)  *B_STR + n0 + gid]);
        unsigned b1 = __float_as_uint(Bs[(k0+tid4+4)*B_STR + n0 + gid]);
        mma_tf32(oc[j], a0,a1,a2,a3, b0,b1);
      }
    }
  }
  float* dst = nt ? g_v : g_k;
  const float* bias = bkv + nt*128;
  int ra = mt*64 + m0 + gid, rb = ra + 8;
#pragma unroll
  for (int j=0;j<8;j++){
    int col = wn*64 + j*8 + 2*tid4;
    float2 w0 = {to_tf32(oc[j][0]+bias[col]), to_tf32(oc[j][1]+bias[col+1])};
    float2 w1 = {to_tf32(oc[j][2]+bias[col]), to_tf32(oc[j][3]+bias[col+1])};
    *(float2*)&dst[(size_t)ra*HDD + col] = w0;
    *(float2*)&dst[(size_t)rb*HDD + col] = w1;
  }
}

// ---------------- grouped gather-GEMM: q[slot] = x[tok] @ Wq[e] (tf32 mma) ----------------
__global__ __launch_bounds__(256) void q_mma_kernel(const float* __restrict__ x,
                                                    const float* __restrict__ Wq){
  int e = blockIdx.y, mt = blockIdx.x;
  int cnt = g_ecount[e];
  if (mt*64 >= cnt) return;
  __shared__ float As[64*A_STR];
  __shared__ float Bs[32*B_STR];
  __shared__ int rows[64];
  int tid = threadIdx.x;
  if (tid < 64){
    int mi = mt*64 + tid;
    rows[tid] = (mi < cnt) ? g_elist[g_eoffset[e] + mi] : -1;
  }
  int wid = tid>>5, lane = tid&31;
  int wm = wid&3, wn = wid>>2;
  int gid = lane>>2, tid4 = lane&3;
  int m0 = wm*16;
  float oc[8][4];
#pragma unroll
  for (int j=0;j<8;j++){ oc[j][0]=0.f; oc[j][1]=0.f; oc[j][2]=0.f; oc[j][3]=0.f; }
  const float* Bb = Wq + (size_t)e*DIMD*HDD;
  __syncthreads();

  for (int k0g=0;k0g<DIMD;k0g+=32){
#pragma unroll
    for (int j=0;j<2;j++){
      int f = tid + j*256; int row = f>>3, kq = f&7;
      int idx = rows[row];
      float4 r = {0.f,0.f,0.f,0.f};
      if (idx>=0){
        float4 v = *(const float4*)&x[(size_t)(idx>>3)*DIMD + k0g + kq*4];
        r.x=to_tf32(v.x); r.y=to_tf32(v.y); r.z=to_tf32(v.z); r.w=to_tf32(v.w);
      }
      *(float4*)&As[row*A_STR + kq*4] = r;
    }
#pragma unroll
    for (int j=0;j<4;j++){
      int f = tid + j*256; int row = f>>5, nq = f&31;
      float4 v = *(const float4*)&Bb[(size_t)(k0g+row)*HDD + nq*4];
      float4 r = {to_tf32(v.x), to_tf32(v.y), to_tf32(v.z), to_tf32(v.w)};
      *(float4*)&Bs[row*B_STR + nq*4] = r;
    }
    __syncthreads();
#pragma unroll
    for (int kt=0;kt<4;kt++){
      int k0 = kt*8;
      unsigned a0 = __float_as_uint(As[(m0+gid)  *A_STR + k0 + tid4]);
      unsigned a1 = __float_as_uint(As[(m0+8+gid)*A_STR + k0 + tid4]);
      unsigned a2 = __float_as_uint(As[(m0+gid)  *A_STR + k0 + tid4 + 4]);
      unsigned a3 = __float_as_uint(As[(m0+8+gid)*A_STR + k0 + tid4 + 4]);
#pragma unroll
      for (int j=0;j<8;j++){
        int n0 = wn*64 + j*8;
        unsigned b0 = __float_as_uint(Bs[(k0+tid4)  *B_STR + n0 + gid]);
        unsigned b1 = __float_as_uint(Bs[(k0+tid4+4)*B_STR + n0 + gid]);
        mma_tf32(oc[j], a0,a1,a2,a3, b0,b1);
      }
    }
    __syncthreads();
  }
  int ia = rows[m0+gid], ib = rows[m0+8+gid];
#pragma unroll
  for (int j=0;j<8;j++){
    int col = wn*64 + j*8 + 2*tid4;
    if (ia>=0){
      float2 w = {to_tf32(oc[j][0]*ATT_SCALE), to_tf32(oc[j][1]*ATT_SCALE)};
      *(float2*)&g_q[(size_t)ia*HDD + col] = w;
    }
    if (ib>=0){
      float2 w = {to_tf32(oc[j][2]*ATT_SCALE), to_tf32(oc[j][3]*ATT_SCALE)};
      *(float2*)&g_q[(size_t)ib*HDD + col] = w;
    }
  }
}

// ---------------- flash attention (MQA) with tf32 mma.sync ----------------
#define Q_STR 132
#define K_STR 132
#define V_STR 136
#define P_STR 68
#define FLASH_SMEM ((64*Q_STR + 64*K_STR + 64*V_STR + 64*P_STR + 256)*4)
__global__ __launch_bounds__(256, 1) void flash_kernel(){
  int mt = blockIdx.x, h = blockIdx.y, b = blockIdx.z;
  extern __shared__ float sm[];
  float* Qs   = sm;
  float* Ks   = Qs + 64*Q_STR;
  float* Vs   = Ks + 64*K_STR;
  float* Ps   = Vs + 64*V_STR;
  float* pmax = Ps + 64*P_STR;   // [2][64]
  float* psum = pmax + 128;      // [2][64]
  int tid  = threadIdx.x;
  int wid  = tid >> 5, lane = tid & 31;
  int wm = wid & 3, wn = wid >> 2;
  int gid = lane >> 2, tid4 = lane & 3;
  int m0 = wm*16;

#pragma unroll
  for (int j=0;j<8;j++){
    int f = tid + j*256;
    int row = f>>5, dv = f&31;
    float4 qv = *(const float4*)&g_q[((size_t)(b*NN + mt*64 + row)*NH + h)*HDD + dv*4];
    *(float4*)&Qs[row*Q_STR + dv*4] = qv;
  }

  float m_i[2] = {-1e30f, -1e30f}, l_i[2] = {0.f, 0.f};
  float oc[8][4];
#pragma unroll
  for (int j=0;j<8;j++){ oc[j][0]=0.f; oc[j][1]=0.f; oc[j][2]=0.f; oc[j][3]=0.f; }

  for (int nt2=0; nt2<NN/64; nt2++){
    __syncthreads();
#pragma unroll
    for (int j=0;j<8;j++){
      int f = tid + j*256;
      int row = f>>5, dv = f&31;
      size_t grow = (size_t)(b*NN + nt2*64 + row);
      *(float4*)&Ks[row*K_STR + dv*4] = *(const float4*)&g_k[grow*HDD + dv*4];
      *(float4*)&Vs[row*V_STR + dv*4] = *(const float4*)&g_v[grow*HDD + dv*4];
    }
    __syncthreads();

    float sc[4][4];
#pragma unroll
    for (int j=0;j<4;j++){ sc[j][0]=0.f; sc[j][1]=0.f; sc[j][2]=0.f; sc[j][3]=0.f; }
#pragma unroll
    for (int kt=0; kt<16; kt++){
      int k0 = kt*8;
      unsigned a0 = __float_as_uint(Qs[(m0+gid)  *Q_STR + k0 + tid4]);
      unsigned a1 = __float_as_uint(Qs[(m0+8+gid)*Q_STR + k0 + tid4]);
      unsigned a2 = __float_as_uint(Qs[(m0+gid)  *Q_STR + k0 + tid4 + 4]);
      unsigned a3 = __float_as_uint(Qs[(m0+8+gid)*Q_STR + k0 + tid4 + 4]);
#pragma unroll
      for (int j=0;j<4;j++){
        int n0 = wn*32 + j*8;
        unsigned b0 = __float_as_uint(Ks[(n0+gid)*K_STR + k0 + tid4]);
        unsigned b1 = __float_as_uint(Ks[(n0+gid)*K_STR + k0 + tid4 + 4]);
        mma_tf32(sc[j], a0,a1,a2,a3, b0,b1);
      }
    }

    float mx0 = fmaxf(fmaxf(sc[0][0],sc[0][1]), fmaxf(sc[1][0],sc[1][1]));
    mx0 = fmaxf(mx0, fmaxf(fmaxf(sc[2][0],sc[2][1]), fmaxf(sc[3][0],sc[3][1])));
    float mx1 = fmaxf(fmaxf(sc[0][2],sc[0][3]), fmaxf(sc[1][2],sc[1][3]));
    mx1 = fmaxf(mx1, fmaxf(fmaxf(sc[2][2],sc[2][3]), fmaxf(sc[3][2],sc[3][3])));
    mx0 = fmaxf(mx0, __shfl_xor_sync(0xffffffffu, mx0, 1));
    mx0 = fmaxf(mx0, __shfl_xor_sync(0xffffffffu, mx0, 2));
    mx1 = fmaxf(mx1, __shfl_xor_sync(0xffffffffu, mx1, 1));
    mx1 = fmaxf(mx1, __shfl_xor_sync(0xffffffffu, mx1, 2));
    if (tid4==0){
      pmax[wn*64 + m0 + gid]     = mx0;
      pmax[wn*64 + m0 + 8 + gid] = mx1;
    }
    __syncthreads();
    float mn0 = fmaxf(m_i[0], fmaxf(pmax[m0+gid],   pmax[64+m0+gid]));
    float mn1 = fmaxf(m_i[1], fmaxf(pmax[m0+8+gid], pmax[64+m0+8+gid]));

    float rs0 = 0.f, rs1 = 0.f;
#pragma unroll
    for (int j=0;j<4;j++){
      int cc = wn*32 + j*8 + 2*tid4;
      float p00 = __expf(sc[j][0]-mn0), p01 = __expf(sc[j][1]-mn0);
      float p10 = __expf(sc[j][2]-mn1), p11 = __expf(sc[j][3]-mn1);
      rs0 += p00 + p01; rs1 += p10 + p11;
      Ps[(m0+gid)*P_STR   + cc]   = to_tf32(p00);
      Ps[(m0+gid)*P_STR   + cc+1] = to_tf32(p01);
      Ps[(m0+8+gid)*P_STR + cc]   = to_tf32(p10);
      Ps[(m0+8+gid)*P_STR + cc+1] = to_tf32(p11);
    }
    rs0 += __shfl_xor_sync(0xffffffffu, rs0, 1);
    rs0 += __shfl_xor_sync(0xffffffffu, rs0, 2);
    rs1 += __shfl_xor_sync(0xffffffffu, rs1, 1);
    rs1 += __shfl_xor_sync(0xffffffffu, rs1, 2);
    if (tid4==0){
      psum[wn*64 + m0 + gid]     = rs0;
      psum[wn*64 + m0 + 8 + gid] = rs1;
    }
    __syncthreads();
    float gs0 = psum[m0+gid]   + psum[64+m0+gid];
    float gs1 = psum[m0+8+gid] + psum[64+m0+8+gid];
    float al0 = __expf(m_i[0]-mn0), al1 = __expf(m_i[1]-mn1);
    l_i[0] = l_i[0]*al0 + gs0; l_i[1] = l_i[1]*al1 + gs1;
    m_i[0] = mn0; m_i[1] = mn1;
#pragma unroll
    for (int j=0;j<8;j++){ oc[j][0]*=al0; oc[j][1]*=al0; oc[j][2]*=al1; oc[j][3]*=al1; }

#pragma unroll
    for (int kt=0; kt<8; kt++){
      int k0 = kt*8;
      unsigned a0 = __float_as_uint(Ps[(m0+gid)  *P_STR + k0 + tid4]);
      unsigned a1 = __float_as_uint(Ps[(m0+8+gid)*P_STR + k0 + tid4]);
      unsigned a2 = __float_as_uint(Ps[(m0+gid)  *P_STR + k0 + tid4 + 4]);
      unsigned a3 = __float_as_uint(Ps[(m0+8+gid)*P_STR + k0 + tid4 + 4]);
#pragma unroll
      for (int j=0;j<8;j++){
        int n0 = wn*64 + j*8;
        unsigned b0 = __float_as_uint(Vs[(k0+tid4)  *V_STR + n0 + gid]);
        unsigned b1 = __float_as_uint(Vs[(k0+tid4+4)*V_STR + n0 + gid]);
        mma_tf32(oc[j], a0,a1,a2,a3, b0,b1);
      }
    }
  }

  float inv0 = 1.f/l_i[0], inv1 = 1.f/l_i[1];
  size_t base0 = ((size_t)(b*NN + mt*64 + m0 + gid)*NH + h)*HDD;
  size_t base1 = ((size_t)(b*NN + mt*64 + m0 + 8 + gid)*NH + h)*HDD;
#pragma unroll
  for (int j=0;j<8;j++){
    int col = wn*64 + j*8 + 2*tid4;
    *(float2*)&g_att[base0 + col] = make_float2(oc[j][0]*inv0, oc[j][1]*inv0);
    *(float2*)&g_att[base1 + col] = make_float2(oc[j][2]*inv1, oc[j][3]*inv1);
  }
}

// ---------------- grouped output GEMM: y += (gate*att) @ Wo[e] (tf32 mma, atomic epilogue) ----------------
__global__ __launch_bounds__(256) void y_mma_kernel(const float* __restrict__ Wo,
                                                    float* __restrict__ y){
  int e = blockIdx.y, mt = blockIdx.x, zc = blockIdx.z;   // zc: 128-col slice of DIMD
  int cnt = g_ecount[e];
  if (mt*64 >= cnt) return;
  __shared__ float As[64*A_STR];
  __shared__ float Bs[32*B_STR];
  __shared__ int rows[64];
  __shared__ float gr[64];
  int tid = threadIdx.x;
  if (tid < 64){
    int mi = mt*64 + tid;
    int idx = (mi < cnt) ? g_elist[g_eoffset[e] + mi] : -1;
    rows[tid] = idx;
    gr[tid] = (idx>=0) ? g_gates[idx] : 0.f;
  }
  int wid = tid>>5, lane = tid&31;
  int wm = wid&3, wn = wid>>2;
  int gid = lane>>2, tid4 = lane&3;
  int m0 = wm*16;
  float oc[8][4];
#pragma unroll
  for (int j=0;j<8;j++){ oc[j][0]=0.f; oc[j][1]=0.f; oc[j][2]=0.f; oc[j][3]=0.f; }
  const float* Bb = Wo + (size_t)e*HDD*DIMD + zc*128;
  __syncthreads();

  for (int k0g=0;k0g<HDD;k0g+=32){
#pragma unroll
    for (int j=0;j<2;j++){
      int f = tid + j*256; int row = f>>3, kq = f&7;
      int idx = rows[row];
      float4 r = {0.f,0.f,0.f,0.f};
      if (idx>=0){
        float4 v = *(const float4*)&g_att[(size_t)idx*HDD + k0g + kq*4];
        float g = gr[row];
        r.x=to_tf32(v.x*g); r.y=to_tf32(v.y*g); r.z=to_tf32(v.z*g); r.w=to_tf32(v.w*g);
      }
      *(float4*)&As[row*A_STR + kq*4] = r;
    }
#pragma unroll
    for (int j=0;j<4;j++){
      int f = tid + j*256; int row = f>>5, nq = f&31;
      float4 v = *(const float4*)&Bb[(size_t)(k0g+row)*DIMD + nq*4];
      float4 r = {to_tf32(v.x), to_tf32(v.y), to_tf32(v.z), to_tf32(v.w)};
      *(float4*)&Bs[row*B_STR + nq*4] = r;
    }
    __syncthreads();
#pragma unroll
    for (int kt=0;kt<4;kt++){
      int k0 = kt*8;
      unsigned a0 = __float_as_uint(As[(m0+gid)  *A_STR + k0 + tid4]);
      unsigned a1 = __float_as_uint(As[(m0+8+gid)*A_STR + k0 + tid4]);
      unsigned a2 = __float_as_uint(As[(m0+gid)  *A_STR + k0 + tid4 + 4]);
      unsigned a3 = __float_as_uint(As[(m0+8+gid)*A_STR + k0 + tid4 + 4]);
#pragma unroll
      for (int j=0;j<8;j++){
        int n0 = wn*64 + j*8;
        unsigned b0 = __float_as_uint(Bs[(k0+tid4)  *B_STR + n0 + gid]);
        unsigned b1 = __float_as_uint(Bs[(k0+tid4+4)*B_STR + n0 + gid]);
        mma_tf32(oc[j], a0,a1,a2,a3, b0,b1);
      }
    }
    __syncthreads();
  }
  int ia = rows[m0+gid], ib = rows[m0+8+gid];
#pragma unroll
  for (int j=0;j<8;j++){
    int col = zc*128 + wn*64 + j*8 + 2*tid4;
    if (ia>=0){
      int tok = ia >> 3;
      atomicAdd(&y[(size_t)tok*DIMD + col],     oc[j][0]);
      atomicAdd(&y[(size_t)tok*DIMD + col + 1], oc[j][1]);
    }
    if (ib>=0){
      int tok = ib >> 3;
      atomicAdd(&y[(size_t)tok*DIMD + col],     oc[j][2]);
      atomicAdd(&y[(size_t)tok*DIMD + col + 1], oc[j][3]);
    }
  }
}

// ---------------- aux loss ----------------
__global__ void aux_kernel(float* __restrict__ out, int out_size){
  int lane = threadIdx.x;
  float v = 0.f;
  if (lane < NE) v = ((float)g_ecount[lane]/(float)NT) * (g_psum[lane]/(float)NT);
  v = warp_sum(v);
  if (lane==0 && out_size > NT*DIMD)
    out[(size_t)NT*DIMD] = 0.1f*NE*v + 0.001f*(g_zsum/(float)NT);
}

// ---------------- launcher ----------------
extern "C" void kernel_launch(void* const* d_in, const int* in_sizes, int n_in,
                              void* d_out, int out_size){
  const float* x       = (const float*)d_in[0];
  const int*   task_bh = (const int*)  d_in[1];
  const float* Wg      = (const float*)d_in[2];
  const float* Wq      = (const float*)d_in[3];
  const float* Wo      = (const float*)d_in[4];
  const float* Wkv     = (const float*)d_in[5];
  const float* bkv     = (const float*)d_in[6];
  float* y = (float*)d_out;

  cudaFuncSetAttribute(flash_kernel, cudaFuncAttributeMaxDynamicSharedMemorySize, FLASH_SMEM);

  cudaMemsetAsync(y, 0, (size_t)NT*DIMD*sizeof(float));
  zero_small_kernel<<<1, 64>>>();
  transpose_wg_kernel<<<NTASKS*NE, 256>>>(Wg);
  gating_kernel<<<NT, 256>>>(x, task_bh);
  offsets_kernel<<<1, 32>>>();
  scatter_kernel<<<(NT*NH)/256, 256>>>();
  kv_mma_kernel<<<dim3(NT/64, 2), 256>>>(x, Wkv, bkv);
  q_mma_kernel<<<dim3(NT/64, NE), 256>>>(x, Wq);
  flash_kernel<<<dim3(NN/64, NH, BB), 256, FLASH_SMEM>>>();
  y_mma_kernel<<<dim3(NT/64, NE, DIMD/128), 256>>>(Wo, y);
  aux_kernel<<<1, 32>>>(y, out_size);
}

// round 15
// speedup vs baseline: 3.1229x; 1.0559x over previous
#include <cuda_runtime.h>
#include <math.h>

#define BB 4
#define NN 2048
#define DIMD 1024
#define NE 24
#define NH 8
#define HDD 128
#define NTASKS 9
#define NT (BB*NN)                    /* 8192 tokens */
#define ATT_SCALE 0.08838834764831843f /* 128^-0.5 */

// ---------------- device scratch (static: no allocations allowed) ----------------
static __device__ float g_WgT[(size_t)NTASKS*NE*DIMD];       // gate weights transposed [t][e][d]
static __device__ float g_q  [(size_t)NT*NH*HDD];            // gathered queries, tf32, pre-scaled
static __device__ float g_k  [(size_t)NT*HDD];               // tf32
static __device__ float g_v  [(size_t)NT*HDD];               // tf32
static __device__ float g_att[(size_t)NT*NH*HDD];            // attention output (fp32)
static __device__ float g_gates[NT*NH];
static __device__ int   g_topi [NT*NH];
static __device__ int   g_ecount[NE];
static __device__ int   g_eoffset[NE];
static __device__ int   g_efill[NE];
static __device__ int   g_elist[NT*NH];                      // slot -> (tok*8+h)
static __device__ float g_psum[NE];
static __device__ float g_zsum;

// ---------------- helpers ----------------
__device__ __forceinline__ float warp_sum(float v){
#pragma unroll
  for (int off=16; off; off>>=1) v += __shfl_xor_sync(0xffffffffu, v, off);
  return v;
}
__device__ __forceinline__ float warp_max(float v){
#pragma unroll
  for (int off=16; off; off>>=1) v = fmaxf(v, __shfl_xor_sync(0xffffffffu, v, off));
  return v;
}
__device__ __forceinline__ float to_tf32(float x){
  unsigned u;
  asm("cvt.rna.tf32.f32 %0, %1;" : "=r"(u) : "f"(x));
  return __uint_as_float(u);
}
__device__ __forceinline__ void mma_tf32(float c[4],
    unsigned a0, unsigned a1, unsigned a2, unsigned a3,
    unsigned b0, unsigned b1){
  asm volatile("mma.sync.aligned.m16n8k8.row.col.f32.tf32.tf32.f32 "
    "{%0,%1,%2,%3}, {%4,%5,%6,%7}, {%8,%9}, {%0,%1,%2,%3};"
    : "+f"(c[0]), "+f"(c[1]), "+f"(c[2]), "+f"(c[3])
    : "r"(a0), "r"(a1), "r"(a2), "r"(a3), "r"(b0), "r"(b1));
}

#define A_STR 36    /* = 4 mod 32: conflict-free for gid-row A frags */
#define B_STR 136   /* = 8 mod 32: conflict-free for tid4-row B frags */

// ---------------- small setup kernels ----------------
__global__ void zero_small_kernel(){
  int t = threadIdx.x;
  if (t < NE){ g_ecount[t]=0; g_efill[t]=0; g_psum[t]=0.f; }
  if (t==0) g_zsum = 0.f;
}

__global__ void transpose_wg_kernel(const float* __restrict__ Wg){
  int te = blockIdx.x;                // t*NE + e
  int t = te / NE, e = te % NE;
  for (int d = threadIdx.x; d < DIMD; d += blockDim.x)
    g_WgT[(size_t)te*DIMD + d] = Wg[((size_t)t*DIMD + d)*NE + e];
}

// ---------------- gating: logits, softmax stats, top-8, gates ----------------
__global__ __launch_bounds__(256) void gating_kernel(const float* __restrict__ x,
                                                     const int* __restrict__ task_bh){
  int tok = blockIdx.x;
  int b = tok / NN;
  __shared__ float xs[DIMD];
  __shared__ float lg[NE];
  int tid = threadIdx.x;
  {
    int i = tid*4;
    *(float4*)&xs[i] = *(const float4*)&x[(size_t)tok*DIMD + i];
  }
  __syncthreads();
  int task = task_bh[b];
  int wid = tid>>5, lane = tid&31;
#pragma unroll
  for (int i=0;i<3;i++){
    int e = wid*3+i;
    const float* w = g_WgT + ((size_t)task*NE + e)*DIMD;
    float s = 0.f;
#pragma unroll
    for (int d=lane*4; d<DIMD; d+=128){
      float4 a = *(const float4*)&xs[d];
      float4 wv = *(const float4*)&w[d];
      s += a.x*wv.x + a.y*wv.y + a.z*wv.z + a.w*wv.w;
    }
    s = warp_sum(s);
    if (lane==0) lg[e] = s;
  }
  __syncthreads();
  if (wid==0){
    float v = (lane<NE)? lg[lane] : -1e30f;
    float m = warp_max(v);
    float ex = (lane<NE)? __expf(v-m) : 0.f;
    float se = warp_sum(ex);
    float lse = m + logf(se);
    if (lane<NE) atomicAdd(&g_psum[lane], ex/se);
    if (lane==0) atomicAdd(&g_zsum, lse*lse);
  }
  if (tid==0){
    float loc[NE];
#pragma unroll
    for (int e=0;e<NE;e++) loc[e]=lg[e];
    int sel[NH]; float sv[NH];
#pragma unroll
    for (int h=0;h<NH;h++){
      float best = -1e30f; int idx = 0;
      for (int e=0;e<NE;e++){ if (loc[e] > best){ best=loc[e]; idx=e; } }
      sel[h]=idx; sv[h]=best; loc[idx] = -1e30f;
    }
    float mx = sv[0];
    float pe[NH]; float den = 0.f;
#pragma unroll
    for (int h=0;h<NH;h++){ pe[h]=__expf(sv[h]-mx); den += pe[h]; }
    float inv = 1.f/den;
#pragma unroll
    for (int h=0;h<NH;h++){
      g_gates[tok*NH+h] = pe[h]*inv;
      g_topi [tok*NH+h] = sel[h];
      atomicAdd(&g_ecount[sel[h]], 1);
    }
  }
}

__global__ void offsets_kernel(){
  if (threadIdx.x==0){
    int run=0;
    for (int e=0;e<NE;e++){ g_eoffset[e]=run; run += g_ecount[e]; }
  }
}

__global__ void scatter_kernel(){
  int i = blockIdx.x*blockDim.x + threadIdx.x;
  if (i < NT*NH){
    int e = g_topi[i];
    int pos = atomicAdd(&g_efill[e], 1);
    g_elist[g_eoffset[e]+pos] = i;     // i = tok*8 + h
  }
}

// ---------------- kv = x @ Wkv + bkv  (tf32 mma, tf32-rounded output) ----------------
__global__ __launch_bounds__(256) void kv_mma_kernel(const float* __restrict__ x,
                                                     const float* __restrict__ Wkv,
                                                     const float* __restrict__ bkv){
  __shared__ float As[64*A_STR];
  __shared__ float Bs[32*B_STR];
  int mt = blockIdx.x, nt = blockIdx.y;   // nt: 0 -> k, 1 -> v
  int tid = threadIdx.x;
  int wid = tid>>5, lane = tid&31;
  int wm = wid&3, wn = wid>>2;
  int gid = lane>>2, tid4 = lane&3;
  int m0 = wm*16;
  float oc[8][4];
#pragma unroll
  for (int j=0;j<8;j++){ oc[j][0]=0.f; oc[j][1]=0.f; oc[j][2]=0.f; oc[j][3]=0.f; }
  const float* Arow = x + (size_t)mt*64*DIMD;

  for (int k0g=0;k0g<DIMD;k0g+=32){
    __syncthreads();
#pragma unroll
    for (int j=0;j<2;j++){
      int f = tid + j*256; int row = f>>3, kq = f&7;
      float4 v = *(const float4*)&Arow[(size_t)row*DIMD + k0g + kq*4];
      float4 r = {to_tf32(v.x), to_tf32(v.y), to_tf32(v.z), to_tf32(v.w)};
      *(float4*)&As[row*A_STR + kq*4] = r;
    }
#pragma unroll
    for (int j=0;j<4;j++){
      int f = tid + j*256; int row = f>>5, nq = f&31;
      float4 v = *(const float4*)&Wkv[(size_t)(k0g+row)*(2*HDD) + nt*128 + nq*4];
      float4 r = {to_tf32(v.x), to_tf32(v.y), to_tf32(v.z), to_tf32(v.w)};
      *(float4*)&Bs[row*B_STR + nq*4] = r;
    }
    __syncthreads();
#pragma unroll
    for (int kt=0;kt<4;kt++){
      int k0 = kt*8;
      unsigned a0 = __float_as_uint(As[(m0+gid)  *A_STR + k0 + tid4]);
      unsigned a1 = __float_as_uint(As[(m0+8+gid)*A_STR + k0 + tid4]);
      unsigned a2 = __float_as_uint(As[(m0+gid)  *A_STR + k0 + tid4 + 4]);
      unsigned a3 = __float_as_uint(As[(m0+8+gid)*A_STR + k0 + tid4 + 4]);
#pragma unroll
      for (int j=0;j<8;j++){
        int n0 = wn*64 + j*8;
        unsigned b0 = __float_as_uint(Bs[(k0+tid4)  *B_STR + n0 + gid]);
        unsigned b1 = __float_as_uint(Bs[(k0+tid4+4)*B_STR + n0 + gid]);
        mma_tf32(oc[j], a0,a1,a2,a3, b0,b1);
      }
    }
  }
  float* dst = nt ? g_v : g_k;
  const float* bias = bkv + nt*128;
  int ra = mt*64 + m0 + gid, rb = ra + 8;
#pragma unroll
  for (int j=0;j<8;j++){
    int col = wn*64 + j*8 + 2*tid4;
    float2 w0 = {to_tf32(oc[j][0]+bias[col]), to_tf32(oc[j][1]+bias[col+1])};
    float2 w1 = {to_tf32(oc[j][2]+bias[col]), to_tf32(oc[j][3]+bias[col+1])};
    *(float2*)&dst[(size_t)ra*HDD + col] = w0;
    *(float2*)&dst[(size_t)rb*HDD + col] = w1;
  }
}

// ---------------- grouped gather-GEMM: q[slot] = x[tok] @ Wq[e] (tf32 mma) ----------------
__global__ __launch_bounds__(256) void q_mma_kernel(const float* __restrict__ x,
                                                    const float* __restrict__ Wq){
  int e = blockIdx.y, mt = blockIdx.x;
  int cnt = g_ecount[e];
  if (mt*64 >= cnt) return;
  __shared__ float As[64*A_STR];
  __shared__ float Bs[32*B_STR];
  __shared__ int rows[64];
  int tid = threadIdx.x;
  if (tid < 64){
    int mi = mt*64 + tid;
    rows[tid] = (mi < cnt) ? g_elist[g_eoffset[e] + mi] : -1;
  }
  int wid = tid>>5, lane = tid&31;
  int wm = wid&3, wn = wid>>2;
  int gid = lane>>2, tid4 = lane&3;
  int m0 = wm*16;
  float oc[8][4];
#pragma unroll
  for (int j=0;j<8;j++){ oc[j][0]=0.f; oc[j][1]=0.f; oc[j][2]=0.f; oc[j][3]=0.f; }
  const float* Bb = Wq + (size_t)e*DIMD*HDD;
  __syncthreads();

  for (int k0g=0;k0g<DIMD;k0g+=32){
#pragma unroll
    for (int j=0;j<2;j++){
      int f = tid + j*256; int row = f>>3, kq = f&7;
      int idx = rows[row];
      float4 r = {0.f,0.f,0.f,0.f};
      if (idx>=0){
        float4 v = *(const float4*)&x[(size_t)(idx>>3)*DIMD + k0g + kq*4];
        r.x=to_tf32(v.x); r.y=to_tf32(v.y); r.z=to_tf32(v.z); r.w=to_tf32(v.w);
      }
      *(float4*)&As[row*A_STR + kq*4] = r;
    }
#pragma unroll
    for (int j=0;j<4;j++){
      int f = tid + j*256; int row = f>>5, nq = f&31;
      float4 v = *(const float4*)&Bb[(size_t)(k0g+row)*HDD + nq*4];
      float4 r = {to_tf32(v.x), to_tf32(v.y), to_tf32(v.z), to_tf32(v.w)};
      *(float4*)&Bs[row*B_STR + nq*4] = r;
    }
    __syncthreads();
#pragma unroll
    for (int kt=0;kt<4;kt++){
      int k0 = kt*8;
      unsigned a0 = __float_as_uint(As[(m0+gid)  *A_STR + k0 + tid4]);
      unsigned a1 = __float_as_uint(As[(m0+8+gid)*A_STR + k0 + tid4]);
      unsigned a2 = __float_as_uint(As[(m0+gid)  *A_STR + k0 + tid4 + 4]);
      unsigned a3 = __float_as_uint(As[(m0+8+gid)*A_STR + k0 + tid4 + 4]);
#pragma unroll
      for (int j=0;j<8;j++){
        int n0 = wn*64 + j*8;
        unsigned b0 = __float_as_uint(Bs[(k0+tid4)  *B_STR + n0 + gid]);
        unsigned b1 = __float_as_uint(Bs[(k0+tid4+4)*B_STR + n0 + gid]);
        mma_tf32(oc[j], a0,a1,a2,a3, b0,b1);
      }
    }
    __syncthreads();
  }
  int ia = rows[m0+gid], ib = rows[m0+8+gid];
#pragma unroll
  for (int j=0;j<8;j++){
    int col = wn*64 + j*8 + 2*tid4;
    if (ia>=0){
      float2 w = {to_tf32(oc[j][0]*ATT_SCALE), to_tf32(oc[j][1]*ATT_SCALE)};
      *(float2*)&g_q[(size_t)ia*HDD + col] = w;
    }
    if (ib>=0){
      float2 w = {to_tf32(oc[j][2]*ATT_SCALE), to_tf32(oc[j][3]*ATT_SCALE)};
      *(float2*)&g_q[(size_t)ib*HDD + col] = w;
    }
  }
}

// ---------------- flash attention (MQA) with tf32 mma.sync ----------------
// Ps aliases Ks: Ks is dead after the S-mma loop, and the pmax __syncthreads
// already orders the last Ks read before the first Ps write. smem drops
// 118KB -> 101KB -> 2 CTAs/SM.
#define Q_STR 132
#define K_STR 132
#define V_STR 136
#define P_STR 68
#define FLASH_SMEM ((64*Q_STR + 64*K_STR + 64*V_STR + 256)*4)
__global__ __launch_bounds__(256, 2) void flash_kernel(){
  int mt = blockIdx.x, h = blockIdx.y, b = blockIdx.z;
  extern __shared__ float sm[];
  float* Qs   = sm;
  float* Ks   = Qs + 64*Q_STR;
  float* Vs   = Ks + 64*K_STR;
  float* Ps   = Ks;              // alias: Ks dead once S is computed
  float* pmax = Vs + 64*V_STR;   // [2][64]
  float* psum = pmax + 128;      // [2][64]
  int tid  = threadIdx.x;
  int wid  = tid >> 5, lane = tid & 31;
  int wm = wid & 3, wn = wid >> 2;
  int gid = lane >> 2, tid4 = lane & 3;
  int m0 = wm*16;

#pragma unroll
  for (int j=0;j<8;j++){
    int f = tid + j*256;
    int row = f>>5, dv = f&31;
    float4 qv = *(const float4*)&g_q[((size_t)(b*NN + mt*64 + row)*NH + h)*HDD + dv*4];
    *(float4*)&Qs[row*Q_STR + dv*4] = qv;
  }

  float m_i[2] = {-1e30f, -1e30f}, l_i[2] = {0.f, 0.f};
  float oc[8][4];
#pragma unroll
  for (int j=0;j<8;j++){ oc[j][0]=0.f; oc[j][1]=0.f; oc[j][2]=0.f; oc[j][3]=0.f; }

  for (int nt2=0; nt2<NN/64; nt2++){
    __syncthreads();   // prior P*V consumed (Ps aliases Ks); Qs ready on iter 0
#pragma unroll
    for (int j=0;j<8;j++){
      int f = tid + j*256;
      int row = f>>5, dv = f&31;
      size_t grow = (size_t)(b*NN + nt2*64 + row);
      *(float4*)&Ks[row*K_STR + dv*4] = *(const float4*)&g_k[grow*HDD + dv*4];
      *(float4*)&Vs[row*V_STR + dv*4] = *(const float4*)&g_v[grow*HDD + dv*4];
    }
    __syncthreads();

    float sc[4][4];
#pragma unroll
    for (int j=0;j<4;j++){ sc[j][0]=0.f; sc[j][1]=0.f; sc[j][2]=0.f; sc[j][3]=0.f; }
#pragma unroll
    for (int kt=0; kt<16; kt++){
      int k0 = kt*8;
      unsigned a0 = __float_as_uint(Qs[(m0+gid)  *Q_STR + k0 + tid4]);
      unsigned a1 = __float_as_uint(Qs[(m0+8+gid)*Q_STR + k0 + tid4]);
      unsigned a2 = __float_as_uint(Qs[(m0+gid)  *Q_STR + k0 + tid4 + 4]);
      unsigned a3 = __float_as_uint(Qs[(m0+8+gid)*Q_STR + k0 + tid4 + 4]);
#pragma unroll
      for (int j=0;j<4;j++){
        int n0 = wn*32 + j*8;
        unsigned b0 = __float_as_uint(Ks[(n0+gid)*K_STR + k0 + tid4]);
        unsigned b1 = __float_as_uint(Ks[(n0+gid)*K_STR + k0 + tid4 + 4]);
        mma_tf32(sc[j], a0,a1,a2,a3, b0,b1);
      }
    }

    float mx0 = fmaxf(fmaxf(sc[0][0],sc[0][1]), fmaxf(sc[1][0],sc[1][1]));
    mx0 = fmaxf(mx0, fmaxf(fmaxf(sc[2][0],sc[2][1]), fmaxf(sc[3][0],sc[3][1])));
    float mx1 = fmaxf(fmaxf(sc[0][2],sc[0][3]), fmaxf(sc[1][2],sc[1][3]));
    mx1 = fmaxf(mx1, fmaxf(fmaxf(sc[2][2],sc[2][3]), fmaxf(sc[3][2],sc[3][3])));
    mx0 = fmaxf(mx0, __shfl_xor_sync(0xffffffffu, mx0, 1));
    mx0 = fmaxf(mx0, __shfl_xor_sync(0xffffffffu, mx0, 2));
    mx1 = fmaxf(mx1, __shfl_xor_sync(0xffffffffu, mx1, 1));
    mx1 = fmaxf(mx1, __shfl_xor_sync(0xffffffffu, mx1, 2));
    if (tid4==0){
      pmax[wn*64 + m0 + gid]     = mx0;
      pmax[wn*64 + m0 + 8 + gid] = mx1;
    }
    __syncthreads();   // orders last Ks read before Ps (alias) writes below
    float mn0 = fmaxf(m_i[0], fmaxf(pmax[m0+gid],   pmax[64+m0+gid]));
    float mn1 = fmaxf(m_i[1], fmaxf(pmax[m0+8+gid], pmax[64+m0+8+gid]));

    float rs0 = 0.f, rs1 = 0.f;
#pragma unroll
    for (int j=0;j<4;j++){
      int cc = wn*32 + j*8 + 2*tid4;
      float p00 = __expf(sc[j][0]-mn0), p01 = __expf(sc[j][1]-mn0);
      float p10 = __expf(sc[j][2]-mn1), p11 = __expf(sc[j][3]-mn1);
      rs0 += p00 + p01; rs1 += p10 + p11;
      Ps[(m0+gid)*P_STR   + cc]   = to_tf32(p00);
      Ps[(m0+gid)*P_STR   + cc+1] = to_tf32(p01);
      Ps[(m0+8+gid)*P_STR + cc]   = to_tf32(p10);
      Ps[(m0+8+gid)*P_STR + cc+1] = to_tf32(p11);
    }
    rs0 += __shfl_xor_sync(0xffffffffu, rs0, 1);
    rs0 += __shfl_xor_sync(0xffffffffu, rs0, 2);
    rs1 += __shfl_xor_sync(0xffffffffu, rs1, 1);
    rs1 += __shfl_xor_sync(0xffffffffu, rs1, 2);
    if (tid4==0){
      psum[wn*64 + m0 + gid]     = rs0;
      psum[wn*64 + m0 + 8 + gid] = rs1;
    }
    __syncthreads();
    float gs0 = psum[m0+gid]   + psum[64+m0+gid];
    float gs1 = psum[m0+8+gid] + psum[64+m0+8+gid];
    float al0 = __expf(m_i[0]-mn0), al1 = __expf(m_i[1]-mn1);
    l_i[0] = l_i[0]*al0 + gs0; l_i[1] = l_i[1]*al1 + gs1;
    m_i[0] = mn0; m_i[1] = mn1;
#pragma unroll
    for (int j=0;j<8;j++){ oc[j][0]*=al0; oc[j][1]*=al0; oc[j][2]*=al1; oc[j][3]*=al1; }

#pragma unroll
    for (int kt=0; kt<8; kt++){
      int k0 = kt*8;
      unsigned a0 = __float_as_uint(Ps[(m0+gid)  *P_STR + k0 + tid4]);
      unsigned a1 = __float_as_uint(Ps[(m0+8+gid)*P_STR + k0 + tid4]);
      unsigned a2 = __float_as_uint(Ps[(m0+gid)  *P_STR + k0 + tid4 + 4]);
      unsigned a3 = __float_as_uint(Ps[(m0+8+gid)*P_STR + k0 + tid4 + 4]);
#pragma unroll
      for (int j=0;j<8;j++){
        int n0 = wn*64 + j*8;
        unsigned b0 = __float_as_uint(Vs[(k0+tid4)  *V_STR + n0 + gid]);
        unsigned b1 = __float_as_uint(Vs[(k0+tid4+4)*V_STR + n0 + gid]);
        mma_tf32(oc[j], a0,a1,a2,a3, b0,b1);
      }
    }
  }

  float inv0 = 1.f/l_i[0], inv1 = 1.f/l_i[1];
  size_t base0 = ((size_t)(b*NN + mt*64 + m0 + gid)*NH + h)*HDD;
  size_t base1 = ((size_t)(b*NN + mt*64 + m0 + 8 + gid)*NH + h)*HDD;
#pragma unroll
  for (int j=0;j<8;j++){
    int col = wn*64 + j*8 + 2*tid4;
    *(float2*)&g_att[base0 + col] = make_float2(oc[j][0]*inv0, oc[j][1]*inv0);
    *(float2*)&g_att[base1 + col] = make_float2(oc[j][2]*inv1, oc[j][3]*inv1);
  }
}

// ---------------- grouped output GEMM: y += (gate*att) @ Wo[e] (tf32 mma, atomic epilogue) ----------------
__global__ __launch_bounds__(256) void y_mma_kernel(const float* __restrict__ Wo,
                                                    float* __restrict__ y){
  int e = blockIdx.y, mt = blockIdx.x, zc = blockIdx.z;   // zc: 128-col slice of DIMD
  int cnt = g_ecount[e];
  if (mt*64 >= cnt) return;
  __shared__ float As[64*A_STR];
  __shared__ float Bs[32*B_STR];
  __shared__ int rows[64];
  __shared__ float gr[64];
  int tid = threadIdx.x;
  if (tid < 64){
    int mi = mt*64 + tid;
    int idx = (mi < cnt) ? g_elist[g_eoffset[e] + mi] : -1;
    rows[tid] = idx;
    gr[tid] = (idx>=0) ? g_gates[idx] : 0.f;
  }
  int wid = tid>>5, lane = tid&31;
  int wm = wid&3, wn = wid>>2;
  int gid = lane>>2, tid4 = lane&3;
  int m0 = wm*16;
  float oc[8][4];
#pragma unroll
  for (int j=0;j<8;j++){ oc[j][0]=0.f; oc[j][1]=0.f; oc[j][2]=0.f; oc[j][3]=0.f; }
  const float* Bb = Wo + (size_t)e*HDD*DIMD + zc*128;
  __syncthreads();

  for (int k0g=0;k0g<HDD;k0g+=32){
#pragma unroll
    for (int j=0;j<2;j++){
      int f = tid + j*256; int row = f>>3, kq = f&7;
      int idx = rows[row];
      float4 r = {0.f,0.f,0.f,0.f};
      if (idx>=0){
        float4 v = *(const float4*)&g_att[(size_t)idx*HDD + k0g + kq*4];
        float g = gr[row];
        r.x=to_tf32(v.x*g); r.y=to_tf32(v.y*g); r.z=to_tf32(v.z*g); r.w=to_tf32(v.w*g);
      }
      *(float4*)&As[row*A_STR + kq*4] = r;
    }
#pragma unroll
    for (int j=0;j<4;j++){
      int f = tid + j*256; int row = f>>5, nq = f&31;
      float4 v = *(const float4*)&Bb[(size_t)(k0g+row)*DIMD + nq*4];
      float4 r = {to_tf32(v.x), to_tf32(v.y), to_tf32(v.z), to_tf32(v.w)};
      *(float4*)&Bs[row*B_STR + nq*4] = r;
    }
    __syncthreads();
#pragma unroll
    for (int kt=0;kt<4;kt++){
      int k0 = kt*8;
      unsigned a0 = __float_as_uint(As[(m0+gid)  *A_STR + k0 + tid4]);
      unsigned a1 = __float_as_uint(As[(m0+8+gid)*A_STR + k0 + tid4]);
      unsigned a2 = __float_as_uint(As[(m0+gid)  *A_STR + k0 + tid4 + 4]);
      unsigned a3 = __float_as_uint(As[(m0+8+gid)*A_STR + k0 + tid4 + 4]);
#pragma unroll
      for (int j=0;j<8;j++){
        int n0 = wn*64 + j*8;
        unsigned b0 = __float_as_uint(Bs[(k0+tid4)  *B_STR + n0 + gid]);
        unsigned b1 = __float_as_uint(Bs[(k0+tid4+4)*B_STR + n0 + gid]);
        mma_tf32(oc[j], a0,a1,a2,a3, b0,b1);
      }
    }
    __syncthreads();
  }
  int ia = rows[m0+gid], ib = rows[m0+8+gid];
#pragma unroll
  for (int j=0;j<8;j++){
    int col = zc*128 + wn*64 + j*8 + 2*tid4;
    if (ia>=0){
      int tok = ia >> 3;
      atomicAdd(&y[(size_t)tok*DIMD + col],     oc[j][0]);
      atomicAdd(&y[(size_t)tok*DIMD + col + 1], oc[j][1]);
    }
    if (ib>=0){
      int tok = ib >> 3;
      atomicAdd(&y[(size_t)tok*DIMD + col],     oc[j][2]);
      atomicAdd(&y[(size_t)tok*DIMD + col + 1], oc[j][3]);
    }
  }
}

// ---------------- aux loss ----------------
__global__ void aux_kernel(float* __restrict__ out, int out_size){
  int lane = threadIdx.x;
  float v = 0.f;
  if (lane < NE) v = ((float)g_ecount[lane]/(float)NT) * (g_psum[lane]/(float)NT);
  v = warp_sum(v);
  if (lane==0 && out_size > NT*DIMD)
    out[(size_t)NT*DIMD] = 0.1f*NE*v + 0.001f*(g_zsum/(float)NT);
}

// ---------------- launcher ----------------
extern "C" void kernel_launch(void* const* d_in, const int* in_sizes, int n_in,
                              void* d_out, int out_size){
  const float* x       = (const float*)d_in[0];
  const int*   task_bh = (const int*)  d_in[1];
  const float* Wg      = (const float*)d_in[2];
  const float* Wq      = (const float*)d_in[3];
  const float* Wo      = (const float*)d_in[4];
  const float* Wkv     = (const float*)d_in[5];
  const float* bkv     = (const float*)d_in[6];
  float* y = (float*)d_out;

  cudaFuncSetAttribute(flash_kernel, cudaFuncAttributeMaxDynamicSharedMemorySize, FLASH_SMEM);

  cudaMemsetAsync(y, 0, (size_t)NT*DIMD*sizeof(float));
  zero_small_kernel<<<1, 64>>>();
  transpose_wg_kernel<<<NTASKS*NE, 256>>>(Wg);
  gating_kernel<<<NT, 256>>>(x, task_bh);
  offsets_kernel<<<1, 32>>>();
  scatter_kernel<<<(NT*NH)/256, 256>>>();
  kv_mma_kernel<<<dim3(NT/64, 2), 256>>>(x, Wkv, bkv);
  q_mma_kernel<<<dim3(NT/64, NE), 256>>>(x, Wq);
  flash_kernel<<<dim3(NN/64, NH, BB), 256, FLASH_SMEM>>>();
  y_mma_kernel<<<dim3(NT/64, NE, DIMD/128), 256>>>(Wo, y);
  aux_kernel<<<1, 32>>>(y, out_size);
}

// round 16
// speedup vs baseline: 3.1793x; 1.0181x over previous
#include <cuda_runtime.h>
#include <math.h>

#define BB 4
#define NN 2048
#define DIMD 1024
#define NE 24
#define NH 8
#define HDD 128
#define NTASKS 9
#define NT (BB*NN)                    /* 8192 tokens */
#define ATT_SCALE 0.08838834764831843f /* 128^-0.5 */

// ---------------- device scratch (static: no allocations allowed) ----------------
static __device__ float g_WgT[(size_t)NTASKS*NE*DIMD];       // gate weights transposed [t][e][d]
static __device__ float g_q  [(size_t)NT*NH*HDD];            // gathered queries, tf32, pre-scaled
static __device__ float g_k  [(size_t)NT*HDD];               // tf32
static __device__ float g_v  [(size_t)NT*HDD];               // tf32
static __device__ float g_att[(size_t)NT*NH*HDD];            // attention output (fp32)
static __device__ float g_gates[NT*NH];
static __device__ int   g_topi [NT*NH];
static __device__ int   g_ecount[NE];
static __device__ int   g_eoffset[NE];
static __device__ int   g_efill[NE];
static __device__ int   g_elist[NT*NH];                      // slot -> (tok*8+h)
static __device__ float g_psum[NE];
static __device__ float g_zsum;

// ---------------- helpers ----------------
__device__ __forceinline__ float warp_sum(float v){
#pragma unroll
  for (int off=16; off; off>>=1) v += __shfl_xor_sync(0xffffffffu, v, off);
  return v;
}
__device__ __forceinline__ float warp_max(float v){
#pragma unroll
  for (int off=16; off; off>>=1) v = fmaxf(v, __shfl_xor_sync(0xffffffffu, v, off));
  return v;
}
__device__ __forceinline__ float to_tf32(float x){
  unsigned u;
  asm("cvt.rna.tf32.f32 %0, %1;" : "=r"(u) : "f"(x));
  return __uint_as_float(u);
}
__device__ __forceinline__ void mma_tf32(float c[4],
    unsigned a0, unsigned a1, unsigned a2, unsigned a3,
    unsigned b0, unsigned b1){
  asm volatile("mma.sync.aligned.m16n8k8.row.col.f32.tf32.tf32.f32 "
    "{%0,%1,%2,%3}, {%4,%5,%6,%7}, {%8,%9}, {%0,%1,%2,%3};"
    : "+f"(c[0]), "+f"(c[1]), "+f"(c[2]), "+f"(c[3])
    : "r"(a0), "r"(a1), "r"(a2), "r"(a3), "r"(b0), "r"(b1));
}
__device__ __forceinline__ void red_add_f32x2(float* addr, float a, float b){
  asm volatile("red.global.add.v2.f32 [%0], {%1, %2};"
    :: "l"(addr), "f"(a), "f"(b) : "memory");
}

#define A_STR 36    /* = 4 mod 32: conflict-free for gid-row A frags */
#define B_STR 136   /* = 8 mod 32: conflict-free for tid4-row B frags */

// ---------------- small setup kernels ----------------
__global__ void zero_small_kernel(){
  int t = threadIdx.x;
  if (t < NE){ g_ecount[t]=0; g_efill[t]=0; g_psum[t]=0.f; }
  if (t==0) g_zsum = 0.f;
}

__global__ void transpose_wg_kernel(const float* __restrict__ Wg){
  int te = blockIdx.x;                // t*NE + e
  int t = te / NE, e = te % NE;
  for (int d = threadIdx.x; d < DIMD; d += blockDim.x)
    g_WgT[(size_t)te*DIMD + d] = Wg[((size_t)t*DIMD + d)*NE + e];
}

// ---------------- gating: logits, softmax stats, top-8, gates ----------------
__global__ __launch_bounds__(256) void gating_kernel(const float* __restrict__ x,
                                                     const int* __restrict__ task_bh){
  int tok = blockIdx.x;
  int b = tok / NN;
  __shared__ float xs[DIMD];
  __shared__ float lg[NE];
  int tid = threadIdx.x;
  {
    int i = tid*4;
    *(float4*)&xs[i] = *(const float4*)&x[(size_t)tok*DIMD + i];
  }
  __syncthreads();
  int task = task_bh[b];
  int wid = tid>>5, lane = tid&31;
#pragma unroll
  for (int i=0;i<3;i++){
    int e = wid*3+i;
    const float* w = g_WgT + ((size_t)task*NE + e)*DIMD;
    float s = 0.f;
#pragma unroll
    for (int d=lane*4; d<DIMD; d+=128){
      float4 a = *(const float4*)&xs[d];
      float4 wv = *(const float4*)&w[d];
      s += a.x*wv.x + a.y*wv.y + a.z*wv.z + a.w*wv.w;
    }
    s = warp_sum(s);
    if (lane==0) lg[e] = s;
  }
  __syncthreads();
  if (wid==0){
    float v = (lane<NE)? lg[lane] : -1e30f;
    float m = warp_max(v);
    float ex = (lane<NE)? __expf(v-m) : 0.f;
    float se = warp_sum(ex);
    float lse = m + logf(se);
    if (lane<NE) atomicAdd(&g_psum[lane], ex/se);
    if (lane==0) atomicAdd(&g_zsum, lse*lse);
  }
  if (tid==0){
    float loc[NE];
#pragma unroll
    for (int e=0;e<NE;e++) loc[e]=lg[e];
    int sel[NH]; float sv[NH];
#pragma unroll
    for (int h=0;h<NH;h++){
      float best = -1e30f; int idx = 0;
      for (int e=0;e<NE;e++){ if (loc[e] > best){ best=loc[e]; idx=e; } }
      sel[h]=idx; sv[h]=best; loc[idx] = -1e30f;
    }
    float mx = sv[0];
    float pe[NH]; float den = 0.f;
#pragma unroll
    for (int h=0;h<NH;h++){ pe[h]=__expf(sv[h]-mx); den += pe[h]; }
    float inv = 1.f/den;
#pragma unroll
    for (int h=0;h<NH;h++){
      g_gates[tok*NH+h] = pe[h]*inv;
      g_topi [tok*NH+h] = sel[h];
      atomicAdd(&g_ecount[sel[h]], 1);
    }
  }
}

__global__ void offsets_kernel(){
  if (threadIdx.x==0){
    int run=0;
    for (int e=0;e<NE;e++){ g_eoffset[e]=run; run += g_ecount[e]; }
  }
}

__global__ void scatter_kernel(){
  int i = blockIdx.x*blockDim.x + threadIdx.x;
  if (i < NT*NH){
    int e = g_topi[i];
    int pos = atomicAdd(&g_efill[e], 1);
    g_elist[g_eoffset[e]+pos] = i;     // i = tok*8 + h
  }
}

// ---------------- kv = x @ Wkv + bkv  (tf32 mma, tf32-rounded output) ----------------
__global__ __launch_bounds__(256) void kv_mma_kernel(const float* __restrict__ x,
                                                     const float* __restrict__ Wkv,
                                                     const float* __restrict__ bkv){
  __shared__ float As[64*A_STR];
  __shared__ float Bs[32*B_STR];
  int mt = blockIdx.x, nt = blockIdx.y;   // nt: 0 -> k, 1 -> v
  int tid = threadIdx.x;
  int wid = tid>>5, lane = tid&31;
  int wm = wid&3, wn = wid>>2;
  int gid = lane>>2, tid4 = lane&3;
  int m0 = wm*16;
  float oc[8][4];
#pragma unroll
  for (int j=0;j<8;j++){ oc[j][0]=0.f; oc[j][1]=0.f; oc[j][2]=0.f; oc[j][3]=0.f; }
  const float* Arow = x + (size_t)mt*64*DIMD;

  for (int k0g=0;k0g<DIMD;k0g+=32){
    __syncthreads();
#pragma unroll
    for (int j=0;j<2;j++){
      int f = tid + j*256; int row = f>>3, kq = f&7;
      float4 v = *(const float4*)&Arow[(size_t)row*DIMD + k0g + kq*4];
      float4 r = {to_tf32(v.x), to_tf32(v.y), to_tf32(v.z), to_tf32(v.w)};
      *(float4*)&As[row*A_STR + kq*4] = r;
    }
#pragma unroll
    for (int j=0;j<4;j++){
      int f = tid + j*256; int row = f>>5, nq = f&31;
      float4 v = *(const float4*)&Wkv[(size_t)(k0g+row)*(2*HDD) + nt*128 + nq*4];
      float4 r = {to_tf32(v.x), to_tf32(v.y), to_tf32(v.z), to_tf32(v.w)};
      *(float4*)&Bs[row*B_STR + nq*4] = r;
    }
    __syncthreads();
#pragma unroll
    for (int kt=0;kt<4;kt++){
      int k0 = kt*8;
      unsigned a0 = __float_as_uint(As[(m0+gid)  *A_STR + k0 + tid4]);
      unsigned a1 = __float_as_uint(As[(m0+8+gid)*A_STR + k0 + tid4]);
      unsigned a2 = __float_as_uint(As[(m0+gid)  *A_STR + k0 + tid4 + 4]);
      unsigned a3 = __float_as_uint(As[(m0+8+gid)*A_STR + k0 + tid4 + 4]);
#pragma unroll
      for (int j=0;j<8;j++){
        int n0 = wn*64 + j*8;
        unsigned b0 = __float_as_uint(Bs[(k0+tid4)  *B_STR + n0 + gid]);
        unsigned b1 = __float_as_uint(Bs[(k0+tid4+4)*B_STR + n0 + gid]);
        mma_tf32(oc[j], a0,a1,a2,a3, b0,b1);
      }
    }
  }
  float* dst = nt ? g_v : g_k;
  const float* bias = bkv + nt*128;
  int ra = mt*64 + m0 + gid, rb = ra + 8;
#pragma unroll
  for (int j=0;j<8;j++){
    int col = wn*64 + j*8 + 2*tid4;
    float2 w0 = {to_tf32(oc[j][0]+bias[col]), to_tf32(oc[j][1]+bias[col+1])};
    float2 w1 = {to_tf32(oc[j][2]+bias[col]), to_tf32(oc[j][3]+bias[col+1])};
    *(float2*)&dst[(size_t)ra*HDD + col] = w0;
    *(float2*)&dst[(size_t)rb*HDD + col] = w1;
  }
}

// ---------------- grouped gather-GEMM: q[slot] = x[tok] @ Wq[e] (tf32 mma) ----------------
__global__ __launch_bounds__(256) void q_mma_kernel(const float* __restrict__ x,
                                                    const float* __restrict__ Wq){
  int e = blockIdx.y, mt = blockIdx.x;
  int cnt = g_ecount[e];
  if (mt*64 >= cnt) return;
  __shared__ float As[64*A_STR];
  __shared__ float Bs[32*B_STR];
  __shared__ int rows[64];
  int tid = threadIdx.x;
  if (tid < 64){
    int mi = mt*64 + tid;
    rows[tid] = (mi < cnt) ? g_elist[g_eoffset[e] + mi] : -1;
  }
  int wid = tid>>5, lane = tid&31;
  int wm = wid&3, wn = wid>>2;
  int gid = lane>>2, tid4 = lane&3;
  int m0 = wm*16;
  float oc[8][4];
#pragma unroll
  for (int j=0;j<8;j++){ oc[j][0]=0.f; oc[j][1]=0.f; oc[j][2]=0.f; oc[j][3]=0.f; }
  const float* Bb = Wq + (size_t)e*DIMD*HDD;
  __syncthreads();

  for (int k0g=0;k0g<DIMD;k0g+=32){
#pragma unroll
    for (int j=0;j<2;j++){
      int f = tid + j*256; int row = f>>3, kq = f&7;
      int idx = rows[row];
      float4 r = {0.f,0.f,0.f,0.f};
      if (idx>=0){
        float4 v = *(const float4*)&x[(size_t)(idx>>3)*DIMD + k0g + kq*4];
        r.x=to_tf32(v.x); r.y=to_tf32(v.y); r.z=to_tf32(v.z); r.w=to_tf32(v.w);
      }
      *(float4*)&As[row*A_STR + kq*4] = r;
    }
#pragma unroll
    for (int j=0;j<4;j++){
      int f = tid + j*256; int row = f>>5, nq = f&31;
      float4 v = *(const float4*)&Bb[(size_t)(k0g+row)*HDD + nq*4];
      float4 r = {to_tf32(v.x), to_tf32(v.y), to_tf32(v.z), to_tf32(v.w)};
      *(float4*)&Bs[row*B_STR + nq*4] = r;
    }
    __syncthreads();
#pragma unroll
    for (int kt=0;kt<4;kt++){
      int k0 = kt*8;
      unsigned a0 = __float_as_uint(As[(m0+gid)  *A_STR + k0 + tid4]);
      unsigned a1 = __float_as_uint(As[(m0+8+gid)*A_STR + k0 + tid4]);
      unsigned a2 = __float_as_uint(As[(m0+gid)  *A_STR + k0 + tid4 + 4]);
      unsigned a3 = __float_as_uint(As[(m0+8+gid)*A_STR + k0 + tid4 + 4]);
#pragma unroll
      for (int j=0;j<8;j++){
        int n0 = wn*64 + j*8;
        unsigned b0 = __float_as_uint(Bs[(k0+tid4)  *B_STR + n0 + gid]);
        unsigned b1 = __float_as_uint(Bs[(k0+tid4+4)*B_STR + n0 + gid]);
        mma_tf32(oc[j], a0,a1,a2,a3, b0,b1);
      }
    }
    __syncthreads();
  }
  int ia = rows[m0+gid], ib = rows[m0+8+gid];
#pragma unroll
  for (int j=0;j<8;j++){
    int col = wn*64 + j*8 + 2*tid4;
    if (ia>=0){
      float2 w = {to_tf32(oc[j][0]*ATT_SCALE), to_tf32(oc[j][1]*ATT_SCALE)};
      *(float2*)&g_q[(size_t)ia*HDD + col] = w;
    }
    if (ib>=0){
      float2 w = {to_tf32(oc[j][2]*ATT_SCALE), to_tf32(oc[j][3]*ATT_SCALE)};
      *(float2*)&g_q[(size_t)ib*HDD + col] = w;
    }
  }
}

// ---------------- flash attention (MQA) with tf32 mma.sync ----------------
// Ps aliases Ks: Ks is dead after the S-mma loop, and the pmax __syncthreads
// already orders the last Ks read before the first Ps write. smem drops
// 118KB -> 101KB -> 2 CTAs/SM.
#define Q_STR 132
#define K_STR 132
#define V_STR 136
#define P_STR 68
#define FLASH_SMEM ((64*Q_STR + 64*K_STR + 64*V_STR + 256)*4)
__global__ __launch_bounds__(256, 2) void flash_kernel(){
  int mt = blockIdx.x, h = blockIdx.y, b = blockIdx.z;
  extern __shared__ float sm[];
  float* Qs   = sm;
  float* Ks   = Qs + 64*Q_STR;
  float* Vs   = Ks + 64*K_STR;
  float* Ps   = Ks;              // alias: Ks dead once S is computed
  float* pmax = Vs + 64*V_STR;   // [2][64]
  float* psum = pmax + 128;      // [2][64]
  int tid  = threadIdx.x;
  int wid  = tid >> 5, lane = tid & 31;
  int wm = wid & 3, wn = wid >> 2;
  int gid = lane >> 2, tid4 = lane & 3;
  int m0 = wm*16;

#pragma unroll
  for (int j=0;j<8;j++){
    int f = tid + j*256;
    int row = f>>5, dv = f&31;
    float4 qv = *(const float4*)&g_q[((size_t)(b*NN + mt*64 + row)*NH + h)*HDD + dv*4];
    *(float4*)&Qs[row*Q_STR + dv*4] = qv;
  }

  float m_i[2] = {-1e30f, -1e30f}, l_i[2] = {0.f, 0.f};
  float oc[8][4];
#pragma unroll
  for (int j=0;j<8;j++){ oc[j][0]=0.f; oc[j][1]=0.f; oc[j][2]=0.f; oc[j][3]=0.f; }

  for (int nt2=0; nt2<NN/64; nt2++){
    __syncthreads();   // prior P*V consumed (Ps aliases Ks); Qs ready on iter 0
#pragma unroll
    for (int j=0;j<8;j++){
      int f = tid + j*256;
      int row = f>>5, dv = f&31;
      size_t grow = (size_t)(b*NN + nt2*64 + row);
      *(float4*)&Ks[row*K_STR + dv*4] = *(const float4*)&g_k[grow*HDD + dv*4];
      *(float4*)&Vs[row*V_STR + dv*4] = *(const float4*)&g_v[grow*HDD + dv*4];
    }
    __syncthreads();

    float sc[4][4];
#pragma unroll
    for (int j=0;j<4;j++){ sc[j][0]=0.f; sc[j][1]=0.f; sc[j][2]=0.f; sc[j][3]=0.f; }
#pragma unroll
    for (int kt=0; kt<16; kt++){
      int k0 = kt*8;
      unsigned a0 = __float_as_uint(Qs[(m0+gid)  *Q_STR + k0 + tid4]);
      unsigned a1 = __float_as_uint(Qs[(m0+8+gid)*Q_STR + k0 + tid4]);
      unsigned a2 = __float_as_uint(Qs[(m0+gid)  *Q_STR + k0 + tid4 + 4]);
      unsigned a3 = __float_as_uint(Qs[(m0+8+gid)*Q_STR + k0 + tid4 + 4]);
#pragma unroll
      for (int j=0;j<4;j++){
        int n0 = wn*32 + j*8;
        unsigned b0 = __float_as_uint(Ks[(n0+gid)*K_STR + k0 + tid4]);
        unsigned b1 = __float_as_uint(Ks[(n0+gid)*K_STR + k0 + tid4 + 4]);
        mma_tf32(sc[j], a0,a1,a2,a3, b0,b1);
      }
    }

    float mx0 = fmaxf(fmaxf(sc[0][0],sc[0][1]), fmaxf(sc[1][0],sc[1][1]));
    mx0 = fmaxf(mx0, fmaxf(fmaxf(sc[2][0],sc[2][1]), fmaxf(sc[3][0],sc[3][1])));
    float mx1 = fmaxf(fmaxf(sc[0][2],sc[0][3]), fmaxf(sc[1][2],sc[1][3]));
    mx1 = fmaxf(mx1, fmaxf(fmaxf(sc[2][2],sc[2][3]), fmaxf(sc[3][2],sc[3][3])));
    mx0 = fmaxf(mx0, __shfl_xor_sync(0xffffffffu, mx0, 1));
    mx0 = fmaxf(mx0, __shfl_xor_sync(0xffffffffu, mx0, 2));
    mx1 = fmaxf(mx1, __shfl_xor_sync(0xffffffffu, mx1, 1));
    mx1 = fmaxf(mx1, __shfl_xor_sync(0xffffffffu, mx1, 2));
    if (tid4==0){
      pmax[wn*64 + m0 + gid]     = mx0;
      pmax[wn*64 + m0 + 8 + gid] = mx1;
    }
    __syncthreads();   // orders last Ks read before Ps (alias) writes below
    float mn0 = fmaxf(m_i[0], fmaxf(pmax[m0+gid],   pmax[64+m0+gid]));
    float mn1 = fmaxf(m_i[1], fmaxf(pmax[m0+8+gid], pmax[64+m0+8+gid]));

    float rs0 = 0.f, rs1 = 0.f;
#pragma unroll
    for (int j=0;j<4;j++){
      int cc = wn*32 + j*8 + 2*tid4;
      float p00 = __expf(sc[j][0]-mn0), p01 = __expf(sc[j][1]-mn0);
      float p10 = __expf(sc[j][2]-mn1), p11 = __expf(sc[j][3]-mn1);
      rs0 += p00 + p01; rs1 += p10 + p11;
      Ps[(m0+gid)*P_STR   + cc]   = to_tf32(p00);
      Ps[(m0+gid)*P_STR   + cc+1] = to_tf32(p01);
      Ps[(m0+8+gid)*P_STR + cc]   = to_tf32(p10);
      Ps[(m0+8+gid)*P_STR + cc+1] = to_tf32(p11);
    }
    rs0 += __shfl_xor_sync(0xffffffffu, rs0, 1);
    rs0 += __shfl_xor_sync(0xffffffffu, rs0, 2);
    rs1 += __shfl_xor_sync(0xffffffffu, rs1, 1);
    rs1 += __shfl_xor_sync(0xffffffffu, rs1, 2);
    if (tid4==0){
      psum[wn*64 + m0 + gid]     = rs0;
      psum[wn*64 + m0 + 8 + gid] = rs1;
    }
    __syncthreads();
    float gs0 = psum[m0+gid]   + psum[64+m0+gid];
    float gs1 = psum[m0+8+gid] + psum[64+m0+8+gid];
    float al0 = __expf(m_i[0]-mn0), al1 = __expf(m_i[1]-mn1);
    l_i[0] = l_i[0]*al0 + gs0; l_i[1] = l_i[1]*al1 + gs1;
    m_i[0] = mn0; m_i[1] = mn1;
#pragma unroll
    for (int j=0;j<8;j++){ oc[j][0]*=al0; oc[j][1]*=al0; oc[j][2]*=al1; oc[j][3]*=al1; }

#pragma unroll
    for (int kt=0; kt<8; kt++){
      int k0 = kt*8;
      unsigned a0 = __float_as_uint(Ps[(m0+gid)  *P_STR + k0 + tid4]);
      unsigned a1 = __float_as_uint(Ps[(m0+8+gid)*P_STR + k0 + tid4]);
      unsigned a2 = __float_as_uint(Ps[(m0+gid)  *P_STR + k0 + tid4 + 4]);
      unsigned a3 = __float_as_uint(Ps[(m0+8+gid)*P_STR + k0 + tid4 + 4]);
#pragma unroll
      for (int j=0;j<8;j++){
        int n0 = wn*64 + j*8;
        unsigned b0 = __float_as_uint(Vs[(k0+tid4)  *V_STR + n0 + gid]);
        unsigned b1 = __float_as_uint(Vs[(k0+tid4+4)*V_STR + n0 + gid]);
        mma_tf32(oc[j], a0,a1,a2,a3, b0,b1);
      }
    }
  }

  float inv0 = 1.f/l_i[0], inv1 = 1.f/l_i[1];
  size_t base0 = ((size_t)(b*NN + mt*64 + m0 + gid)*NH + h)*HDD;
  size_t base1 = ((size_t)(b*NN + mt*64 + m0 + 8 + gid)*NH + h)*HDD;
#pragma unroll
  for (int j=0;j<8;j++){
    int col = wn*64 + j*8 + 2*tid4;
    *(float2*)&g_att[base0 + col] = make_float2(oc[j][0]*inv0, oc[j][1]*inv0);
    *(float2*)&g_att[base1 + col] = make_float2(oc[j][2]*inv1, oc[j][3]*inv1);
  }
}

// ---------------- grouped output GEMM: y += (gate*att) @ Wo[e] (tf32 mma, f32x2 red epilogue) ----------------
__global__ __launch_bounds__(256) void y_mma_kernel(const float* __restrict__ Wo,
                                                    float* __restrict__ y){
  int e = blockIdx.y, mt = blockIdx.x, zc = blockIdx.z;   // zc: 128-col slice of DIMD
  int cnt = g_ecount[e];
  if (mt*64 >= cnt) return;
  __shared__ float As[64*A_STR];
  __shared__ float Bs[32*B_STR];
  __shared__ int rows[64];
  __shared__ float gr[64];
  int tid = threadIdx.x;
  if (tid < 64){
    int mi = mt*64 + tid;
    int idx = (mi < cnt) ? g_elist[g_eoffset[e] + mi] : -1;
    rows[tid] = idx;
    gr[tid] = (idx>=0) ? g_gates[idx] : 0.f;
  }
  int wid = tid>>5, lane = tid&31;
  int wm = wid&3, wn = wid>>2;
  int gid = lane>>2, tid4 = lane&3;
  int m0 = wm*16;
  float oc[8][4];
#pragma unroll
  for (int j=0;j<8;j++){ oc[j][0]=0.f; oc[j][1]=0.f; oc[j][2]=0.f; oc[j][3]=0.f; }
  const float* Bb = Wo + (size_t)e*HDD*DIMD + zc*128;
  __syncthreads();

  for (int k0g=0;k0g<HDD;k0g+=32){
#pragma unroll
    for (int j=0;j<2;j++){
      int f = tid + j*256; int row = f>>3, kq = f&7;
      int idx = rows[row];
      float4 r = {0.f,0.f,0.f,0.f};
      if (idx>=0){
        float4 v = *(const float4*)&g_att[(size_t)idx*HDD + k0g + kq*4];
        float g = gr[row];
        r.x=to_tf32(v.x*g); r.y=to_tf32(v.y*g); r.z=to_tf32(v.z*g); r.w=to_tf32(v.w*g);
      }
      *(float4*)&As[row*A_STR + kq*4] = r;
    }
#pragma unroll
    for (int j=0;j<4;j++){
      int f = tid + j*256; int row = f>>5, nq = f&31;
      float4 v = *(const float4*)&Bb[(size_t)(k0g+row)*DIMD + nq*4];
      float4 r = {to_tf32(v.x), to_tf32(v.y), to_tf32(v.z), to_tf32(v.w)};
      *(float4*)&Bs[row*B_STR + nq*4] = r;
    }
    __syncthreads();
#pragma unroll
    for (int kt=0;kt<4;kt++){
      int k0 = kt*8;
      unsigned a0 = __float_as_uint(As[(m0+gid)  *A_STR + k0 + tid4]);
      unsigned a1 = __float_as_uint(As[(m0+8+gid)*A_STR + k0 + tid4]);
      unsigned a2 = __float_as_uint(As[(m0+gid)  *A_STR + k0 + tid4 + 4]);
      unsigned a3 = __float_as_uint(As[(m0+8+gid)*A_STR + k0 + tid4 + 4]);
#pragma unroll
      for (int j=0;j<8;j++){
        int n0 = wn*64 + j*8;
        unsigned b0 = __float_as_uint(Bs[(k0+tid4)  *B_STR + n0 + gid]);
        unsigned b1 = __float_as_uint(Bs[(k0+tid4+4)*B_STR + n0 + gid]);
        mma_tf32(oc[j], a0,a1,a2,a3, b0,b1);
      }
    }
    __syncthreads();
  }
  int ia = rows[m0+gid], ib = rows[m0+8+gid];
#pragma unroll
  for (int j=0;j<8;j++){
    int col = zc*128 + wn*64 + j*8 + 2*tid4;
    if (ia>=0){
      int tok = ia >> 3;
      red_add_f32x2(&y[(size_t)tok*DIMD + col], oc[j][0], oc[j][1]);
    }
    if (ib>=0){
      int tok = ib >> 3;
      red_add_f32x2(&y[(size_t)tok*DIMD + col], oc[j][2], oc[j][3]);
    }
  }
}

// ---------------- aux loss ----------------
__global__ void aux_kernel(float* __restrict__ out, int out_size){
  int lane = threadIdx.x;
  float v = 0.f;
  if (lane < NE) v = ((float)g_ecount[lane]/(float)NT) * (g_psum[lane]/(float)NT);
  v = warp_sum(v);
  if (lane==0 && out_size > NT*DIMD)
    out[(size_t)NT*DIMD] = 0.1f*NE*v + 0.001f*(g_zsum/(float)NT);
}

// ---------------- launcher ----------------
extern "C" void kernel_launch(void* const* d_in, const int* in_sizes, int n_in,
                              void* d_out, int out_size){
  const float* x       = (const float*)d_in[0];
  const int*   task_bh = (const int*)  d_in[1];
  const float* Wg      = (const float*)d_in[2];
  const float* Wq      = (const float*)d_in[3];
  const float* Wo      = (const float*)d_in[4];
  const float* Wkv     = (const float*)d_in[5];
  const float* bkv     = (const float*)d_in[6];
  float* y = (float*)d_out;

  cudaFuncSetAttribute(flash_kernel, cudaFuncAttributeMaxDynamicSharedMemorySize, FLASH_SMEM);

  cudaMemsetAsync(y, 0, (size_t)NT*DIMD*sizeof(float));
  zero_small_kernel<<<1, 64>>>();
  transpose_wg_kernel<<<NTASKS*NE, 256>>>(Wg);
  gating_kernel<<<NT, 256>>>(x, task_bh);
  offsets_kernel<<<1, 32>>>();
  scatter_kernel<<<(NT*NH)/256, 256>>>();
  kv_mma_kernel<<<dim3(NT/64, 2), 256>>>(x, Wkv, bkv);
  q_mma_kernel<<<dim3(NT/64, NE), 256>>>(x, Wq);
  flash_kernel<<<dim3(NN/64, NH, BB), 256, FLASH_SMEM>>>();
  y_mma_kernel<<<dim3(NT/64, NE, DIMD/128), 256>>>(Wo, y);
  aux_kernel<<<1, 32>>>(y, out_size);
}